// round 4
// baseline (speedup 1.0000x reference)
#include <cuda_runtime.h>
#include <cuda_bf16.h>
#include <mma.h>
#include <math.h>

using namespace nvcuda;

#define NN    50000
#define EE    800000
#define ETOT  (EE + NN)
#define FIN   78
#define H1C   10
#define D1    (H1C * FIN)   // 780
#define OUT2C 128
#define GC    512
#define SLOPE 0.2f
#define CHUNK 64

// ---------------- scratch ----------------
__device__ float g_h1 [(size_t)NN * D1];
__device__ float g_o1 [(size_t)NN * D1];
__device__ float g_h2 [(size_t)NN * OUT2C];
__device__ float g_o2 [(size_t)NN * OUT2C];
__device__ float g_as1[(size_t)NN * H1C];
__device__ float g_ad1[(size_t)NN * H1C];
__device__ float g_as2[NN];
__device__ float g_ad2[NN];
__device__ int   g_deg[NN + 1];
__device__ int   g_rowptr[NN + 1];
__device__ int   g_cursor[NN];
__device__ int   g_csrsrc[ETOT];
__device__ int   g_gstart[GC + 1];

// ---------------- helpers ----------------
__device__ __forceinline__ void atomicMaxF(float* addr, float val) {
    if (!signbit(val)) atomicMax((int*)addr, __float_as_int(val));
    else               atomicMin((unsigned int*)addr, __float_as_uint(val));
}
__device__ __forceinline__ void edge_nodes(const int* __restrict__ ei, int t, int& s, int& d) {
    if (t < EE) { s = ei[t]; d = ei[EE + t]; }
    else        { s = t - EE; d = t - EE; }
}

__global__ void fill_int(int* p, int v, int n) {
    int i = blockIdx.x * blockDim.x + threadIdx.x;
    if (i < n) p[i] = v;
}

// ---------------- CSR build ----------------
__global__ void hist_kernel(const int* __restrict__ ei, int* __restrict__ deg) {
    int t = blockIdx.x * blockDim.x + threadIdx.x;
    if (t >= ETOT) return;
    int s, d; edge_nodes(ei, t, s, d);
    atomicAdd(&deg[d], 1);
}

__global__ void scan50k(const int* __restrict__ deg, int* __restrict__ rowptr) {
    __shared__ int sh[1024];
    __shared__ int carry_s;
    int tid = threadIdx.x;
    if (tid == 0) carry_s = 0;
    __syncthreads();
    for (int base = 0; base < NN; base += 1024) {
        int i = base + tid;
        int v = (i < NN) ? deg[i] : 0;
        sh[tid] = v;
        __syncthreads();
        #pragma unroll
        for (int o = 1; o < 1024; o <<= 1) {
            int t = (tid >= o) ? sh[tid - o] : 0;
            __syncthreads();
            sh[tid] += t;
            __syncthreads();
        }
        int c = carry_s;
        if (i < NN) rowptr[i] = c + sh[tid] - v;
        __syncthreads();
        if (tid == 0) carry_s = c + sh[1023];
        __syncthreads();
    }
    if (tid == 0) rowptr[NN] = carry_s;
}

__global__ void cursor_copy(const int* __restrict__ rowptr, int* __restrict__ cur) {
    int i = blockIdx.x * blockDim.x + threadIdx.x;
    if (i < NN) cur[i] = rowptr[i];
}

__global__ void csr_scatter(const int* __restrict__ ei, int* __restrict__ cur,
                            int* __restrict__ csrsrc) {
    int t = blockIdx.x * blockDim.x + threadIdx.x;
    if (t >= ETOT) return;
    int s, d; edge_nodes(ei, t, s, d);
    int pos = atomicAdd(&cur[d], 1);
    csrsrc[pos] = s;
}

__global__ void gstart_build(const int* __restrict__ batch, int* __restrict__ gstart) {
    int i = blockIdx.x * blockDim.x + threadIdx.x;
    if (i >= NN) return;
    int b  = batch[i];
    int bp = (i == 0) ? -1 : batch[i - 1];
    for (int g = bp + 1; g <= b; ++g) gstart[g] = i;
    if (i == NN - 1) {
        for (int g = b + 1; g <= GC; ++g) gstart[g] = NN;
    }
}

// ---------------- TF32 tensor-core GEMM ----------------
// C[M,N] = A[M,K] @ B[K,N]. Block 128x128x32, 8 warps, warp tile 32x64.
#define LDA_S 40    // 32 + 8 pad
#define LDB_S 136   // 128 + 8 pad
#define LDST  68    // 64 + 4 pad (boundary staging)

__global__ __launch_bounds__(256) void sgemm_tf32(
    const float* __restrict__ A, const float* __restrict__ B, float* __restrict__ C,
    int M, int K, int Nn)
{
    __shared__ float sm[128 * LDA_S + 32 * LDB_S];   // 9472 floats ≈ 37.9 KB
    float* As = sm;                   // [128][LDA_S]
    float* Bs = sm + 128 * LDA_S;     // [32][LDB_S]

    int tid = threadIdx.x;
    int warp = tid >> 5;
    int warp_m = warp & 3;        // 0..3 -> 32-row slabs
    int warp_n = warp >> 2;       // 0..1 -> 64-col slabs
    int rowBase = blockIdx.y * 128, colBase = blockIdx.x * 128;

    wmma::fragment<wmma::accumulator, 16, 16, 8, float> acc[2][4];
    #pragma unroll
    for (int i = 0; i < 2; i++)
        #pragma unroll
        for (int j = 0; j < 4; j++) wmma::fill_fragment(acc[i][j], 0.f);

    for (int k0 = 0; k0 < K; k0 += 32) {
        // load A 128x32
        #pragma unroll
        for (int i = 0; i < 16; i++) {
            int idx = tid + i * 256;
            int r = idx >> 5, c = idx & 31;
            int gr = rowBase + r, gc = k0 + c;
            float v = (gr < M && gc < K) ? A[(size_t)gr * K + gc] : 0.f;
            As[r * LDA_S + c] = wmma::__float_to_tf32(v);
        }
        // load B 32x128
        #pragma unroll
        for (int i = 0; i < 16; i++) {
            int idx = tid + i * 256;
            int r = idx >> 7, c = idx & 127;
            int gr = k0 + r, gc = colBase + c;
            float v = (gr < K && gc < Nn) ? B[(size_t)gr * Nn + gc] : 0.f;
            Bs[r * LDB_S + c] = wmma::__float_to_tf32(v);
        }
        __syncthreads();

        #pragma unroll
        for (int kk = 0; kk < 32; kk += 8) {
            wmma::fragment<wmma::matrix_a, 16, 16, 8, wmma::precision::tf32, wmma::row_major> af[2];
            wmma::fragment<wmma::matrix_b, 16, 16, 8, wmma::precision::tf32, wmma::row_major> bf[4];
            #pragma unroll
            for (int i = 0; i < 2; i++)
                wmma::load_matrix_sync(af[i], &As[(warp_m * 32 + i * 16) * LDA_S + kk], LDA_S);
            #pragma unroll
            for (int j = 0; j < 4; j++)
                wmma::load_matrix_sync(bf[j], &Bs[kk * LDB_S + warp_n * 64 + j * 16], LDB_S);
            #pragma unroll
            for (int i = 0; i < 2; i++)
                #pragma unroll
                for (int j = 0; j < 4; j++)
                    wmma::mma_sync(acc[i][j], af[i], bf[j], acc[i][j]);
        }
        __syncthreads();
    }

    bool interior = (rowBase + 128 <= M) && (colBase + 128 <= Nn);
    if (interior) {
        #pragma unroll
        for (int i = 0; i < 2; i++)
            #pragma unroll
            for (int j = 0; j < 4; j++) {
                int gr = rowBase + warp_m * 32 + i * 16;
                int gc = colBase + warp_n * 64 + j * 16;
                wmma::store_matrix_sync(&C[(size_t)gr * Nn + gc], acc[i][j], Nn, wmma::mem_row_major);
            }
    } else {
        // stage 64-col halves through smem with bounds-checked copy-out
        for (int p = 0; p < 2; p++) {
            if (warp_n == p) {
                #pragma unroll
                for (int i = 0; i < 2; i++)
                    #pragma unroll
                    for (int j = 0; j < 4; j++)
                        wmma::store_matrix_sync(&sm[(warp_m * 32 + i * 16) * LDST + j * 16],
                                                acc[i][j], LDST, wmma::mem_row_major);
            }
            __syncthreads();
            #pragma unroll
            for (int i = 0; i < 32; i++) {
                int idx = tid + i * 256;          // 8192 = 128*64
                int r = idx >> 6, c = idx & 63;
                int gr = rowBase + r, gc = colBase + p * 64 + c;
                if (gr < M && gc < Nn) C[(size_t)gr * Nn + gc] = sm[r * LDST + c];
            }
            __syncthreads();
        }
    }
}

// ---------------- per-node attention projections ----------------
__global__ void alpha_proj(const float* __restrict__ h,
                           const float* __restrict__ a_src, const float* __restrict__ a_dst,
                           float* __restrict__ as, float* __restrict__ ad,
                           int n, int heads, int dim)
{
    int gw = (blockIdx.x * blockDim.x + threadIdx.x) >> 5;
    int lane = threadIdx.x & 31;
    if (gw >= n * heads) return;
    int node = gw / heads, hd = gw - node * heads;
    const float* hp = h + (size_t)node * heads * dim + (size_t)hd * dim;
    float s1 = 0.f, s2 = 0.f;
    for (int f = lane; f < dim; f += 32) {
        float v = hp[f];
        s1 += v * a_src[hd * dim + f];
        s2 += v * a_dst[hd * dim + f];
    }
    #pragma unroll
    for (int o = 16; o; o >>= 1) {
        s1 += __shfl_down_sync(0xffffffffu, s1, o);
        s2 += __shfl_down_sync(0xffffffffu, s2, o);
    }
    if (lane == 0) { as[gw] = s1; ad[gw] = s2; }
}

// ---------------- layer-1 gather (10 heads, 78 feats) ----------------
__global__ __launch_bounds__(256) void gat_gather1(
    const int* __restrict__ rowptr, const int* __restrict__ csrsrc,
    const float* __restrict__ as, const float* __restrict__ ad,
    const float* __restrict__ h, const float* __restrict__ bias,
    float* __restrict__ out)
{
    int d = blockIdx.x;
    int tid = threadIdx.x;
    int beg = rowptr[d], end = rowptr[d + 1];
    int deg = end - beg;

    __shared__ float m[H1C];
    __shared__ float den[H1C];
    __shared__ float adv[H1C];
    __shared__ int   s_src[CHUNK];
    __shared__ float w[CHUNK][H1C];

    if (tid < H1C) {
        adv[tid] = ad[d * H1C + tid];
        m[tid] = -INFINITY;
        den[tid] = 0.f;
    }
    __syncthreads();

    for (int t = tid; t < deg * H1C; t += 256) {
        int e = t / H1C, hh = t - e * H1C;
        int s = csrsrc[beg + e];
        float v = as[s * H1C + hh] + adv[hh];
        v = v > 0.f ? v : SLOPE * v;
        atomicMaxF(&m[hh], v);
    }
    __syncthreads();

    int f0 = tid, f1 = tid + 256, f2 = tid + 512, f3 = tid + 768;
    int hh0 = f0 / FIN, hh1 = f1 / FIN, hh2 = f2 / FIN;
    int hh3 = (f3 < D1) ? f3 / FIN : 0;
    float acc0 = 0.f, acc1 = 0.f, acc2 = 0.f, acc3 = 0.f;

    for (int cbeg = 0; cbeg < deg; cbeg += CHUNK) {
        int clen = min(CHUNK, deg - cbeg);
        for (int t = tid; t < clen; t += 256) s_src[t] = csrsrc[beg + cbeg + t];
        __syncthreads();
        for (int t = tid; t < clen * H1C; t += 256) {
            int e = t / H1C, hh = t - e * H1C;
            float v = as[s_src[e] * H1C + hh] + adv[hh];
            v = v > 0.f ? v : SLOPE * v;
            float ww = __expf(v - m[hh]);
            w[e][hh] = ww;
            atomicAdd(&den[hh], ww);
        }
        __syncthreads();
        for (int e = 0; e < clen; e++) {
            const float* row = h + (size_t)s_src[e] * D1;
            acc0 += row[f0] * w[e][hh0];
            acc1 += row[f1] * w[e][hh1];
            acc2 += row[f2] * w[e][hh2];
            if (f3 < D1) acc3 += row[f3] * w[e][hh3];
        }
        __syncthreads();
    }

    float* op = out + (size_t)d * D1;
    float v0 = acc0 / (den[hh0] + 1e-16f) + bias[f0];
    float v1 = acc1 / (den[hh1] + 1e-16f) + bias[f1];
    float v2 = acc2 / (den[hh2] + 1e-16f) + bias[f2];
    op[f0] = v0 > 0.f ? v0 : 0.f;
    op[f1] = v1 > 0.f ? v1 : 0.f;
    op[f2] = v2 > 0.f ? v2 : 0.f;
    if (f3 < D1) {
        float v3 = acc3 / (den[hh3] + 1e-16f) + bias[f3];
        op[f3] = v3 > 0.f ? v3 : 0.f;
    }
}

// ---------------- layer-2 gather (1 head, 128 feats) ----------------
#define CHUNK2 128
__global__ __launch_bounds__(128) void gat_gather2(
    const int* __restrict__ rowptr, const int* __restrict__ csrsrc,
    const float* __restrict__ as, const float* __restrict__ ad,
    const float* __restrict__ h, const float* __restrict__ bias,
    float* __restrict__ out)
{
    int d = blockIdx.x;
    int tid = threadIdx.x;
    int beg = rowptr[d], end = rowptr[d + 1];
    int deg = end - beg;

    __shared__ float ms, dens;
    __shared__ int   s_src[CHUNK2];
    __shared__ float w[CHUNK2];

    float adv = ad[d];
    if (tid == 0) { ms = -INFINITY; dens = 0.f; }
    __syncthreads();

    for (int t = tid; t < deg; t += 128) {
        float v = as[csrsrc[beg + t]] + adv;
        v = v > 0.f ? v : SLOPE * v;
        atomicMaxF(&ms, v);
    }
    __syncthreads();
    float mv = ms;
    float acc = 0.f;

    for (int cbeg = 0; cbeg < deg; cbeg += CHUNK2) {
        int clen = min(CHUNK2, deg - cbeg);
        if (tid < clen) {
            int s = csrsrc[beg + cbeg + tid];
            s_src[tid] = s;
            float v = as[s] + adv;
            v = v > 0.f ? v : SLOPE * v;
            float ww = __expf(v - mv);
            w[tid] = ww;
            atomicAdd(&dens, ww);
        }
        __syncthreads();
        for (int e = 0; e < clen; e++)
            acc += h[(size_t)s_src[e] * OUT2C + tid] * w[e];
        __syncthreads();
    }

    float v = acc / (dens + 1e-16f) + bias[tid];
    out[(size_t)d * OUT2C + tid] = v > 0.f ? v : 0.f;
}

// ---------------- fused pool(max) + fc + relu ----------------
__global__ __launch_bounds__(128) void pool_fc(
    const float* __restrict__ o2, const int* __restrict__ gstart,
    const float* __restrict__ W, const float* __restrict__ b,
    float* __restrict__ out)
{
    __shared__ float p[OUT2C];
    int g = blockIdx.x, j = threadIdx.x;
    int beg = gstart[g], end = gstart[g + 1];
    float acc = -INFINITY;
    for (int n = beg; n < end; n++)
        acc = fmaxf(acc, o2[(size_t)n * OUT2C + j]);
    p[j] = (beg < end) ? acc : 0.f;
    __syncthreads();
    float s = b[j];
    #pragma unroll 8
    for (int k = 0; k < OUT2C; k++) s += p[k] * W[k * OUT2C + j];
    out[g * OUT2C + j] = s > 0.f ? s : 0.f;
}

// ---------------- launch ----------------
static inline int cdiv(int a, int b) { return (a + b - 1) / b; }

extern "C" void kernel_launch(void* const* d_in, const int* in_sizes, int n_in,
                              void* d_out, int out_size)
{
    const float* x     = (const float*)d_in[0];
    const int*   ei    = (const int*)  d_in[1];
    const int*   batch = (const int*)  d_in[2];
    const float* W1    = (const float*)d_in[4];
    const float* a_s1  = (const float*)d_in[5];
    const float* a_d1  = (const float*)d_in[6];
    const float* b1    = (const float*)d_in[7];
    const float* W2    = (const float*)d_in[8];
    const float* a_s2  = (const float*)d_in[9];
    const float* a_d2  = (const float*)d_in[10];
    const float* b2    = (const float*)d_in[11];
    const float* fcW   = (const float*)d_in[12];
    const float* fcb   = (const float*)d_in[13];
    float* out = (float*)d_out;

    float *h1, *o1, *h2, *o2, *as1, *ad1, *as2, *ad2;
    int *deg, *rowptr, *cursor, *csrsrc, *gstart;
    cudaGetSymbolAddress((void**)&h1,  g_h1);
    cudaGetSymbolAddress((void**)&o1,  g_o1);
    cudaGetSymbolAddress((void**)&h2,  g_h2);
    cudaGetSymbolAddress((void**)&o2,  g_o2);
    cudaGetSymbolAddress((void**)&as1, g_as1);
    cudaGetSymbolAddress((void**)&ad1, g_ad1);
    cudaGetSymbolAddress((void**)&as2, g_as2);
    cudaGetSymbolAddress((void**)&ad2, g_ad2);
    cudaGetSymbolAddress((void**)&deg,    g_deg);
    cudaGetSymbolAddress((void**)&rowptr, g_rowptr);
    cudaGetSymbolAddress((void**)&cursor, g_cursor);
    cudaGetSymbolAddress((void**)&csrsrc, g_csrsrc);
    cudaGetSymbolAddress((void**)&gstart, g_gstart);

    // ---- CSR build (reused by both layers) ----
    fill_int<<<cdiv(NN + 1, 256), 256>>>(deg, 0, NN + 1);
    hist_kernel<<<cdiv(ETOT, 256), 256>>>(ei, deg);
    scan50k<<<1, 1024>>>(deg, rowptr);
    cursor_copy<<<cdiv(NN, 256), 256>>>(rowptr, cursor);
    csr_scatter<<<cdiv(ETOT, 256), 256>>>(ei, cursor, csrsrc);
    gstart_build<<<cdiv(NN, 256), 256>>>(batch, gstart);

    // ---- layer 1 ----
    {
        dim3 grid(cdiv(D1, 128), cdiv(NN, 128));
        sgemm_tf32<<<grid, 256>>>(x, W1, h1, NN, FIN, D1);
    }
    alpha_proj<<<cdiv(NN * H1C * 32, 256), 256>>>(h1, a_s1, a_d1, as1, ad1, NN, H1C, FIN);
    gat_gather1<<<NN, 256>>>(rowptr, csrsrc, as1, ad1, h1, b1, o1);

    // ---- layer 2 ----
    {
        dim3 grid(cdiv(OUT2C, 128), cdiv(NN, 128));
        sgemm_tf32<<<grid, 256>>>(o1, W2, h2, NN, D1, OUT2C);
    }
    alpha_proj<<<cdiv(NN * 32, 256), 256>>>(h2, a_s2, a_d2, as2, ad2, NN, 1, OUT2C);
    gat_gather2<<<NN, 128>>>(rowptr, csrsrc, as2, ad2, h2, b2, o2);

    // ---- pool + fc ----
    pool_fc<<<GC, OUT2C>>>(o2, gstart, fcW, fcb, out);
}

// round 5
// speedup vs baseline: 1.2590x; 1.2590x over previous
#include <cuda_runtime.h>
#include <cuda_bf16.h>
#include <math.h>

#define NN    50000
#define EE    800000
#define ETOT  (EE + NN)
#define FIN   78
#define H1C   10
#define D1    (H1C * FIN)   // 780
#define OUT2C 128
#define GC    512
#define SLOPE 0.2f
#define CHUNK 64

// ---------------- scratch ----------------
__device__ float g_h1 [(size_t)NN * D1];
__device__ float g_o1 [(size_t)NN * D1];
__device__ float g_h2 [(size_t)NN * OUT2C];
__device__ float g_o2 [(size_t)NN * OUT2C];
__device__ float g_as1[(size_t)NN * H1C];
__device__ float g_ad1[(size_t)NN * H1C];
__device__ float g_as2[NN];
__device__ float g_ad2[NN];
__device__ int   g_deg[NN + 1];      // zero-initialized at load; re-zeroed by cleanup kernel
__device__ int   g_rowptr[NN + 1];
__device__ int   g_cursor[NN];
__device__ int   g_csrsrc[ETOT];
__device__ int   g_gstart[GC + 1];

// ---------------- helpers ----------------
__device__ __forceinline__ void atomicMaxF(float* addr, float val) {
    if (!signbit(val)) atomicMax((int*)addr, __float_as_int(val));
    else               atomicMin((unsigned int*)addr, __float_as_uint(val));
}
__device__ __forceinline__ void edge_nodes(const int* __restrict__ ei, int t, int& s, int& d) {
    if (t < EE) { s = ei[t]; d = ei[EE + t]; }
    else        { s = t - EE; d = t - EE; }
}

// ---------------- CSR build ----------------
__global__ void hist_kernel(const int* __restrict__ ei, int* __restrict__ deg) {
    int t = blockIdx.x * blockDim.x + threadIdx.x;
    if (t >= ETOT) return;
    int s, d; edge_nodes(ei, t, s, d);
    atomicAdd(&deg[d], 1);
}

// exclusive scan over 50k degrees; writes rowptr AND cursor
__global__ void scan50k(const int* __restrict__ deg, int* __restrict__ rowptr,
                        int* __restrict__ cur) {
    __shared__ int sh[1024];
    __shared__ int carry_s;
    int tid = threadIdx.x;
    if (tid == 0) carry_s = 0;
    __syncthreads();
    for (int base = 0; base < NN; base += 1024) {
        int i = base + tid;
        int v = (i < NN) ? deg[i] : 0;
        sh[tid] = v;
        __syncthreads();
        #pragma unroll
        for (int o = 1; o < 1024; o <<= 1) {
            int t = (tid >= o) ? sh[tid - o] : 0;
            __syncthreads();
            sh[tid] += t;
            __syncthreads();
        }
        int c = carry_s;
        if (i < NN) {
            int excl = c + sh[tid] - v;
            rowptr[i] = excl;
            cur[i] = excl;
        }
        __syncthreads();
        if (tid == 0) carry_s = c + sh[1023];
        __syncthreads();
    }
    if (tid == 0) rowptr[NN] = carry_s;
}

__global__ void csr_scatter(const int* __restrict__ ei, int* __restrict__ cur,
                            int* __restrict__ csrsrc) {
    int t = blockIdx.x * blockDim.x + threadIdx.x;
    if (t >= ETOT) return;
    int s, d; edge_nodes(ei, t, s, d);
    int pos = atomicAdd(&cur[d], 1);
    csrsrc[pos] = s;
}

__global__ void gstart_build(const int* __restrict__ batch, int* __restrict__ gstart) {
    int i = blockIdx.x * blockDim.x + threadIdx.x;
    if (i >= NN) return;
    int b  = batch[i];
    int bp = (i == 0) ? -1 : batch[i - 1];
    for (int g = bp + 1; g <= b; ++g) gstart[g] = i;
    if (i == NN - 1) {
        for (int g = b + 1; g <= GC; ++g) gstart[g] = NN;
    }
}

// trailing cleanup: re-zero deg so the next replay starts from a clean state
__global__ void zero_deg(int* __restrict__ deg) {
    int i = blockIdx.x * blockDim.x + threadIdx.x;
    if (i < NN + 1) deg[i] = 0;
}

// ---------------- SGEMM: C[M,N] = A[M,K] @ B[K,N], 128x128x16, 8x8 micro ----
__global__ __launch_bounds__(256) void sgemm128(
    const float* __restrict__ A, const float* __restrict__ B, float* __restrict__ C,
    int M, int K, int Nn)
{
    __shared__ float As[16][132];
    __shared__ float Bs[16][132];
    int tid = threadIdx.x;
    int tx = tid & 15, ty = tid >> 4;
    int rowBase = blockIdx.y * 128, colBase = blockIdx.x * 128;
    float acc[8][8] = {};
    for (int k0 = 0; k0 < K; k0 += 16) {
        #pragma unroll
        for (int i = 0; i < 8; i++) {
            int idx = tid + i * 256;
            int r = idx >> 4, c = idx & 15;
            int gr = rowBase + r, gc = k0 + c;
            As[c][r] = (gr < M && gc < K) ? A[(size_t)gr * K + gc] : 0.f;
        }
        #pragma unroll
        for (int i = 0; i < 8; i++) {
            int idx = tid + i * 256;
            int r = idx >> 7, c = idx & 127;
            int gr = k0 + r, gc = colBase + c;
            Bs[r][c] = (gr < K && gc < Nn) ? B[(size_t)gr * Nn + gc] : 0.f;
        }
        __syncthreads();
        #pragma unroll
        for (int k = 0; k < 16; k++) {
            float a[8], b[8];
            #pragma unroll
            for (int i = 0; i < 8; i++) a[i] = As[k][ty * 8 + i];
            #pragma unroll
            for (int j = 0; j < 8; j++) b[j] = Bs[k][tx * 8 + j];
            #pragma unroll
            for (int i = 0; i < 8; i++)
                #pragma unroll
                for (int j = 0; j < 8; j++) acc[i][j] += a[i] * b[j];
        }
        __syncthreads();
    }
    #pragma unroll
    for (int i = 0; i < 8; i++) {
        int gr = rowBase + ty * 8 + i;
        if (gr >= M) continue;
        #pragma unroll
        for (int j = 0; j < 8; j++) {
            int gc = colBase + tx * 8 + j;
            if (gc < Nn) C[(size_t)gr * Nn + gc] = acc[i][j];
        }
    }
}

// ---------------- per-node attention projections ----------------
__global__ void alpha_proj(const float* __restrict__ h,
                           const float* __restrict__ a_src, const float* __restrict__ a_dst,
                           float* __restrict__ as, float* __restrict__ ad,
                           int n, int heads, int dim)
{
    int gw = (blockIdx.x * blockDim.x + threadIdx.x) >> 5;
    int lane = threadIdx.x & 31;
    if (gw >= n * heads) return;
    int node = gw / heads, hd = gw - node * heads;
    const float* hp = h + (size_t)node * heads * dim + (size_t)hd * dim;
    float s1 = 0.f, s2 = 0.f;
    for (int f = lane; f < dim; f += 32) {
        float v = hp[f];
        s1 += v * a_src[hd * dim + f];
        s2 += v * a_dst[hd * dim + f];
    }
    #pragma unroll
    for (int o = 16; o; o >>= 1) {
        s1 += __shfl_down_sync(0xffffffffu, s1, o);
        s2 += __shfl_down_sync(0xffffffffu, s2, o);
    }
    if (lane == 0) { as[gw] = s1; ad[gw] = s2; }
}

// ---------------- layer-1 gather (10 heads, 78 feats) ----------------
__global__ __launch_bounds__(256) void gat_gather1(
    const int* __restrict__ rowptr, const int* __restrict__ csrsrc,
    const float* __restrict__ as, const float* __restrict__ ad,
    const float* __restrict__ h, const float* __restrict__ bias,
    float* __restrict__ out)
{
    int d = blockIdx.x;
    int tid = threadIdx.x;
    int beg = rowptr[d], end = rowptr[d + 1];
    int deg = end - beg;

    __shared__ float m[H1C];
    __shared__ float den[H1C];
    __shared__ float adv[H1C];
    __shared__ int   s_src[CHUNK];
    __shared__ float w[CHUNK][H1C];

    if (tid < H1C) {
        adv[tid] = ad[d * H1C + tid];
        m[tid] = -INFINITY;
        den[tid] = 0.f;
    }
    __syncthreads();

    int f0 = tid, f1 = tid + 256, f2 = tid + 512, f3 = tid + 768;
    int hh0 = f0 / FIN, hh1 = f1 / FIN, hh2 = f2 / FIN;
    int hh3 = (f3 < D1) ? f3 / FIN : 0;
    float acc0 = 0.f, acc1 = 0.f, acc2 = 0.f, acc3 = 0.f;

    if (deg <= CHUNK) {
        // ---- fast path: single read of `as`, logits cached in smem ----
        for (int t = tid; t < deg; t += 256) s_src[t] = csrsrc[beg + t];
        __syncthreads();
        for (int t = tid; t < deg * H1C; t += 256) {
            int e = t / H1C, hh = t - e * H1C;
            float v = as[s_src[e] * H1C + hh] + adv[hh];
            v = v > 0.f ? v : SLOPE * v;
            w[e][hh] = v;
            atomicMaxF(&m[hh], v);
        }
        __syncthreads();
        for (int t = tid; t < deg * H1C; t += 256) {
            int e = t / H1C, hh = t - e * H1C;
            float ww = __expf(w[e][hh] - m[hh]);
            w[e][hh] = ww;
            atomicAdd(&den[hh], ww);
        }
        __syncthreads();
        for (int e = 0; e < deg; e++) {
            const float* row = h + (size_t)s_src[e] * D1;
            acc0 += row[f0] * w[e][hh0];
            acc1 += row[f1] * w[e][hh1];
            acc2 += row[f2] * w[e][hh2];
            if (f3 < D1) acc3 += row[f3] * w[e][hh3];
        }
    } else {
        // ---- fallback: two-pass chunked ----
        for (int t = tid; t < deg * H1C; t += 256) {
            int e = t / H1C, hh = t - e * H1C;
            int s = csrsrc[beg + e];
            float v = as[s * H1C + hh] + adv[hh];
            v = v > 0.f ? v : SLOPE * v;
            atomicMaxF(&m[hh], v);
        }
        __syncthreads();
        for (int cbeg = 0; cbeg < deg; cbeg += CHUNK) {
            int clen = min(CHUNK, deg - cbeg);
            for (int t = tid; t < clen; t += 256) s_src[t] = csrsrc[beg + cbeg + t];
            __syncthreads();
            for (int t = tid; t < clen * H1C; t += 256) {
                int e = t / H1C, hh = t - e * H1C;
                float v = as[s_src[e] * H1C + hh] + adv[hh];
                v = v > 0.f ? v : SLOPE * v;
                float ww = __expf(v - m[hh]);
                w[e][hh] = ww;
                atomicAdd(&den[hh], ww);
            }
            __syncthreads();
            for (int e = 0; e < clen; e++) {
                const float* row = h + (size_t)s_src[e] * D1;
                acc0 += row[f0] * w[e][hh0];
                acc1 += row[f1] * w[e][hh1];
                acc2 += row[f2] * w[e][hh2];
                if (f3 < D1) acc3 += row[f3] * w[e][hh3];
            }
            __syncthreads();
        }
    }
    __syncthreads();

    float* op = out + (size_t)d * D1;
    float v0 = acc0 / (den[hh0] + 1e-16f) + bias[f0];
    float v1 = acc1 / (den[hh1] + 1e-16f) + bias[f1];
    float v2 = acc2 / (den[hh2] + 1e-16f) + bias[f2];
    op[f0] = v0 > 0.f ? v0 : 0.f;
    op[f1] = v1 > 0.f ? v1 : 0.f;
    op[f2] = v2 > 0.f ? v2 : 0.f;
    if (f3 < D1) {
        float v3 = acc3 / (den[hh3] + 1e-16f) + bias[f3];
        op[f3] = v3 > 0.f ? v3 : 0.f;
    }
}

// ---------------- layer-2 gather (1 head, 128 feats) ----------------
#define CHUNK2 128
__global__ __launch_bounds__(128) void gat_gather2(
    const int* __restrict__ rowptr, const int* __restrict__ csrsrc,
    const float* __restrict__ as, const float* __restrict__ ad,
    const float* __restrict__ h, const float* __restrict__ bias,
    float* __restrict__ out)
{
    int d = blockIdx.x;
    int tid = threadIdx.x;
    int beg = rowptr[d], end = rowptr[d + 1];
    int deg = end - beg;

    __shared__ float ms, dens;
    __shared__ int   s_src[CHUNK2];
    __shared__ float w[CHUNK2];

    float adv = ad[d];
    if (tid == 0) { ms = -INFINITY; dens = 0.f; }
    __syncthreads();

    float acc = 0.f;

    if (deg <= CHUNK2) {
        // fast path: logits cached, single read of `as`
        if (tid < deg) {
            int s = csrsrc[beg + tid];
            s_src[tid] = s;
            float v = as[s] + adv;
            v = v > 0.f ? v : SLOPE * v;
            w[tid] = v;
            atomicMaxF(&ms, v);
        }
        __syncthreads();
        float mv = ms;
        if (tid < deg) {
            float ww = __expf(w[tid] - mv);
            w[tid] = ww;
            atomicAdd(&dens, ww);
        }
        __syncthreads();
        for (int e = 0; e < deg; e++)
            acc += h[(size_t)s_src[e] * OUT2C + tid] * w[e];
    } else {
        for (int t = tid; t < deg; t += 128) {
            float v = as[csrsrc[beg + t]] + adv;
            v = v > 0.f ? v : SLOPE * v;
            atomicMaxF(&ms, v);
        }
        __syncthreads();
        float mv = ms;
        for (int cbeg = 0; cbeg < deg; cbeg += CHUNK2) {
            int clen = min(CHUNK2, deg - cbeg);
            if (tid < clen) {
                int s = csrsrc[beg + cbeg + tid];
                s_src[tid] = s;
                float v = as[s] + adv;
                v = v > 0.f ? v : SLOPE * v;
                float ww = __expf(v - mv);
                w[tid] = ww;
                atomicAdd(&dens, ww);
            }
            __syncthreads();
            for (int e = 0; e < clen; e++)
                acc += h[(size_t)s_src[e] * OUT2C + tid] * w[e];
            __syncthreads();
        }
    }
    __syncthreads();

    float v = acc / (dens + 1e-16f) + bias[tid];
    out[(size_t)d * OUT2C + tid] = v > 0.f ? v : 0.f;
}

// ---------------- fused pool(max) + fc + relu ----------------
__global__ __launch_bounds__(128) void pool_fc(
    const float* __restrict__ o2, const int* __restrict__ gstart,
    const float* __restrict__ W, const float* __restrict__ b,
    float* __restrict__ out)
{
    __shared__ float p[OUT2C];
    int g = blockIdx.x, j = threadIdx.x;
    int beg = gstart[g], end = gstart[g + 1];
    float acc = -INFINITY;
    for (int n = beg; n < end; n++)
        acc = fmaxf(acc, o2[(size_t)n * OUT2C + j]);
    p[j] = (beg < end) ? acc : 0.f;
    __syncthreads();
    float s = b[j];
    #pragma unroll 8
    for (int k = 0; k < OUT2C; k++) s += p[k] * W[k * OUT2C + j];
    out[g * OUT2C + j] = s > 0.f ? s : 0.f;
}

// ---------------- launch ----------------
static inline int cdiv(int a, int b) { return (a + b - 1) / b; }

extern "C" void kernel_launch(void* const* d_in, const int* in_sizes, int n_in,
                              void* d_out, int out_size)
{
    const float* x     = (const float*)d_in[0];
    const int*   ei    = (const int*)  d_in[1];
    const int*   batch = (const int*)  d_in[2];
    const float* W1    = (const float*)d_in[4];
    const float* a_s1  = (const float*)d_in[5];
    const float* a_d1  = (const float*)d_in[6];
    const float* b1    = (const float*)d_in[7];
    const float* W2    = (const float*)d_in[8];
    const float* a_s2  = (const float*)d_in[9];
    const float* a_d2  = (const float*)d_in[10];
    const float* b2    = (const float*)d_in[11];
    const float* fcW   = (const float*)d_in[12];
    const float* fcb   = (const float*)d_in[13];
    float* out = (float*)d_out;

    float *h1, *o1, *h2, *o2, *as1, *ad1, *as2, *ad2;
    int *deg, *rowptr, *cursor, *csrsrc, *gstart;
    cudaGetSymbolAddress((void**)&h1,  g_h1);
    cudaGetSymbolAddress((void**)&o1,  g_o1);
    cudaGetSymbolAddress((void**)&h2,  g_h2);
    cudaGetSymbolAddress((void**)&o2,  g_o2);
    cudaGetSymbolAddress((void**)&as1, g_as1);
    cudaGetSymbolAddress((void**)&ad1, g_ad1);
    cudaGetSymbolAddress((void**)&as2, g_as2);
    cudaGetSymbolAddress((void**)&ad2, g_ad2);
    cudaGetSymbolAddress((void**)&deg,    g_deg);
    cudaGetSymbolAddress((void**)&rowptr, g_rowptr);
    cudaGetSymbolAddress((void**)&cursor, g_cursor);
    cudaGetSymbolAddress((void**)&csrsrc, g_csrsrc);
    cudaGetSymbolAddress((void**)&gstart, g_gstart);

    // deg is zero on entry (zero-init on first call, zero_deg cleanup thereafter)
    // 1-3: CSR build
    hist_kernel<<<cdiv(ETOT, 256), 256>>>(ei, deg);                 // 1
    scan50k<<<1, 1024>>>(deg, rowptr, cursor);                      // 2
    csr_scatter<<<cdiv(ETOT, 256), 256>>>(ei, cursor, csrsrc);      // 3

    // ---- layer 1 ----
    {
        dim3 grid(cdiv(D1, 128), cdiv(NN, 128));
        sgemm128<<<grid, 256>>>(x, W1, h1, NN, FIN, D1);            // 4
    }
    alpha_proj<<<cdiv(NN * H1C * 32, 256), 256>>>(h1, a_s1, a_d1, as1, ad1, NN, H1C, FIN); // 5
    gat_gather1<<<NN, 256>>>(rowptr, csrsrc, as1, ad1, h1, b1, o1); // 6  <- ncu -s 5 target

    // ---- layer 2 ----
    {
        dim3 grid(cdiv(OUT2C, 128), cdiv(NN, 128));
        sgemm128<<<grid, 256>>>(o1, W2, h2, NN, D1, OUT2C);         // 7
    }
    alpha_proj<<<cdiv(NN * 32, 256), 256>>>(h2, a_s2, a_d2, as2, ad2, NN, 1, OUT2C); // 8
    gat_gather2<<<NN, 128>>>(rowptr, csrsrc, as2, ad2, h2, b2, o2); // 9

    // ---- pool + fc ----
    gstart_build<<<cdiv(NN, 256), 256>>>(batch, gstart);            // 10
    pool_fc<<<GC, OUT2C>>>(o2, gstart, fcW, fcb, out);              // 11

    // cleanup for next replay
    zero_deg<<<cdiv(NN + 1, 256), 256>>>(deg);                      // 12
}

// round 6
// speedup vs baseline: 1.3428x; 1.0666x over previous
#include <cuda_runtime.h>
#include <cuda_bf16.h>
#include <math.h>

#define NN    50000
#define EE    800000
#define ETOT  (EE + NN)
#define FIN   78
#define H1C   10
#define D1    (H1C * FIN)   // 780
#define OUT2C 128
#define GC    512
#define SLOPE 0.2f
#define CHUNK 64

// ---------------- scratch ----------------
__device__ float g_agg[(size_t)NN * D1];     // per-dst aggregated x (layer 1)
__device__ float g_o1 [(size_t)NN * D1];     // layer-1 output
__device__ float g_h2 [(size_t)NN * OUT2C];
__device__ float g_o2 [(size_t)NN * OUT2C];
__device__ float g_as1[(size_t)NN * H1C];
__device__ float g_ad1[(size_t)NN * H1C];
__device__ float g_as2[NN];
__device__ float g_ad2[NN];
__device__ float g_p  [20 * FIN];            // projected attention vectors
__device__ int   g_deg[NN + 1];              // zero-init; re-zeroed by cleanup
__device__ int   g_rowptr[NN + 1];
__device__ int   g_cursor[NN];
__device__ int   g_csrsrc[ETOT];
__device__ int   g_gstart[GC + 1];

// ---------------- helpers ----------------
__device__ __forceinline__ void atomicMaxF(float* addr, float val) {
    if (!signbit(val)) atomicMax((int*)addr, __float_as_int(val));
    else               atomicMin((unsigned int*)addr, __float_as_uint(val));
}
__device__ __forceinline__ void edge_nodes(const int* __restrict__ ei, int t, int& s, int& d) {
    if (t < EE) { s = ei[t]; d = ei[EE + t]; }
    else        { s = t - EE; d = t - EE; }
}

// ---------------- CSR build ----------------
__global__ void hist_kernel(const int* __restrict__ ei, int* __restrict__ deg) {
    int t = blockIdx.x * blockDim.x + threadIdx.x;
    if (t >= ETOT) return;
    int s, d; edge_nodes(ei, t, s, d);
    atomicAdd(&deg[d], 1);
}

__global__ void scan50k(const int* __restrict__ deg, int* __restrict__ rowptr,
                        int* __restrict__ cur) {
    __shared__ int sh[1024];
    __shared__ int carry_s;
    int tid = threadIdx.x;
    if (tid == 0) carry_s = 0;
    __syncthreads();
    for (int base = 0; base < NN; base += 1024) {
        int i = base + tid;
        int v = (i < NN) ? deg[i] : 0;
        sh[tid] = v;
        __syncthreads();
        #pragma unroll
        for (int o = 1; o < 1024; o <<= 1) {
            int t = (tid >= o) ? sh[tid - o] : 0;
            __syncthreads();
            sh[tid] += t;
            __syncthreads();
        }
        int c = carry_s;
        if (i < NN) {
            int excl = c + sh[tid] - v;
            rowptr[i] = excl;
            cur[i] = excl;
        }
        __syncthreads();
        if (tid == 0) carry_s = c + sh[1023];
        __syncthreads();
    }
    if (tid == 0) rowptr[NN] = carry_s;
}

__global__ void csr_scatter(const int* __restrict__ ei, int* __restrict__ cur,
                            int* __restrict__ csrsrc) {
    int t = blockIdx.x * blockDim.x + threadIdx.x;
    if (t >= ETOT) return;
    int s, d; edge_nodes(ei, t, s, d);
    int pos = atomicAdd(&cur[d], 1);
    csrsrc[pos] = s;
}

__global__ void gstart_build(const int* __restrict__ batch, int* __restrict__ gstart) {
    int i = blockIdx.x * blockDim.x + threadIdx.x;
    if (i >= NN) return;
    int b  = batch[i];
    int bp = (i == 0) ? -1 : batch[i - 1];
    for (int g = bp + 1; g <= b; ++g) gstart[g] = i;
    if (i == NN - 1) {
        for (int g = b + 1; g <= GC; ++g) gstart[g] = NN;
    }
}

__global__ void zero_deg(int* __restrict__ deg) {
    int i = blockIdx.x * blockDim.x + threadIdx.x;
    if (i < NN + 1) deg[i] = 0;
}

// ---------------- p[o][k] = sum_f W1[k, h*78+f] * a_{src|dst}[h][f] ----------
__global__ void precompute_p(const float* __restrict__ W1,
                             const float* __restrict__ a_src, const float* __restrict__ a_dst,
                             float* __restrict__ p)
{
    int idx = blockIdx.x * blockDim.x + threadIdx.x;   // 20*78 outputs
    if (idx >= 20 * FIN) return;
    int o = idx / FIN, k = idx - o * FIN;
    int h = (o < H1C) ? o : o - H1C;
    const float* av = (o < H1C) ? (a_src + h * FIN) : (a_dst + h * FIN);
    const float* wrow = W1 + (size_t)k * D1 + h * FIN;
    float s = 0.f;
    #pragma unroll 13
    for (int f = 0; f < FIN; f++) s += wrow[f] * av[f];
    p[idx] = s;
}

// ---------------- as1/ad1 from x directly: 32 nodes per block ---------------
__global__ __launch_bounds__(256) void proj1(
    const float* __restrict__ x, const float* __restrict__ p,
    float* __restrict__ as, float* __restrict__ ad)
{
    __shared__ float xs[32][80];
    __shared__ float ps[20][80];
    int tid = threadIdx.x;
    int nodeBase = blockIdx.x * 32;

    for (int idx = tid; idx < 20 * FIN; idx += 256) {
        int o = idx / FIN, k = idx - o * FIN;
        ps[o][k] = p[idx];
    }
    for (int idx = tid; idx < 32 * FIN; idx += 256) {
        int i = idx / FIN, k = idx - i * FIN;
        int n = nodeBase + i;
        xs[i][k] = (n < NN) ? x[(size_t)n * FIN + k] : 0.f;
    }
    __syncthreads();

    for (int s = tid; s < 32 * 20; s += 256) {
        int i = s / 20, o = s - i * 20;
        int n = nodeBase + i;
        if (n >= NN) continue;
        float acc = 0.f;
        #pragma unroll 13
        for (int k = 0; k < FIN; k++) acc += xs[i][k] * ps[o][k];
        if (o < H1C) as[n * H1C + o] = acc;
        else         ad[n * H1C + (o - H1C)] = acc;
    }
}

// ---------------- layer-1 gather: aggregate x rows (78 floats/edge) ---------
// agg[d, h*78+f] = (sum_e alpha_eh * x[src_e][f]);  normalized by den.
__global__ __launch_bounds__(256) void gather1x(
    const int* __restrict__ rowptr, const int* __restrict__ csrsrc,
    const float* __restrict__ as, const float* __restrict__ ad,
    const float* __restrict__ x, float* __restrict__ agg)
{
    int d = blockIdx.x;
    int tid = threadIdx.x;
    int beg = rowptr[d], end = rowptr[d + 1];
    int deg = end - beg;

    __shared__ float m[H1C];
    __shared__ float den[H1C];
    __shared__ float adv[H1C];
    __shared__ int   s_src[CHUNK];
    __shared__ float w[CHUNK][H1C];
    __shared__ float xs[CHUNK][80];

    if (tid < H1C) {
        adv[tid] = ad[d * H1C + tid];
        m[tid] = -INFINITY;
        den[tid] = 0.f;
    }
    __syncthreads();

    // thread's 4 (head, feat) slots: c = tid + 256*q
    int c0 = tid, c1 = tid + 256, c2 = tid + 512, c3 = tid + 768;
    int h0 = c0 / FIN, f0l = c0 - h0 * FIN;
    int h1 = c1 / FIN, f1l = c1 - h1 * FIN;
    int h2 = c2 / FIN, f2l = c2 - h2 * FIN;
    int h3 = (c3 < D1) ? c3 / FIN : 0, f3l = (c3 < D1) ? c3 - h3 * FIN : 0;
    float acc0 = 0.f, acc1 = 0.f, acc2 = 0.f, acc3 = 0.f;

    if (deg <= CHUNK) {
        for (int t = tid; t < deg; t += 256) s_src[t] = csrsrc[beg + t];
        __syncthreads();
        for (int t = tid; t < deg * FIN; t += 256) {
            int e = t / FIN, k = t - e * FIN;
            xs[e][k] = x[(size_t)s_src[e] * FIN + k];
        }
        for (int t = tid; t < deg * H1C; t += 256) {
            int e = t / H1C, hh = t - e * H1C;
            float v = as[s_src[e] * H1C + hh] + adv[hh];
            v = v > 0.f ? v : SLOPE * v;
            w[e][hh] = v;
            atomicMaxF(&m[hh], v);
        }
        __syncthreads();
        for (int t = tid; t < deg * H1C; t += 256) {
            int e = t / H1C, hh = t - e * H1C;
            float ww = __expf(w[e][hh] - m[hh]);
            w[e][hh] = ww;
            atomicAdd(&den[hh], ww);
        }
        __syncthreads();
        for (int e = 0; e < deg; e++) {
            acc0 += xs[e][f0l] * w[e][h0];
            acc1 += xs[e][f1l] * w[e][h1];
            acc2 += xs[e][f2l] * w[e][h2];
            if (c3 < D1) acc3 += xs[e][f3l] * w[e][h3];
        }
    } else {
        // max pass over all edges
        for (int t = tid; t < deg * H1C; t += 256) {
            int e = t / H1C, hh = t - e * H1C;
            int s = csrsrc[beg + e];
            float v = as[s * H1C + hh] + adv[hh];
            v = v > 0.f ? v : SLOPE * v;
            atomicMaxF(&m[hh], v);
        }
        __syncthreads();
        for (int cbeg = 0; cbeg < deg; cbeg += CHUNK) {
            int clen = min(CHUNK, deg - cbeg);
            for (int t = tid; t < clen; t += 256) s_src[t] = csrsrc[beg + cbeg + t];
            __syncthreads();
            for (int t = tid; t < clen * FIN; t += 256) {
                int e = t / FIN, k = t - e * FIN;
                xs[e][k] = x[(size_t)s_src[e] * FIN + k];
            }
            for (int t = tid; t < clen * H1C; t += 256) {
                int e = t / H1C, hh = t - e * H1C;
                float v = as[s_src[e] * H1C + hh] + adv[hh];
                v = v > 0.f ? v : SLOPE * v;
                float ww = __expf(v - m[hh]);
                w[e][hh] = ww;
                atomicAdd(&den[hh], ww);
            }
            __syncthreads();
            for (int e = 0; e < clen; e++) {
                acc0 += xs[e][f0l] * w[e][h0];
                acc1 += xs[e][f1l] * w[e][h1];
                acc2 += xs[e][f2l] * w[e][h2];
                if (c3 < D1) acc3 += xs[e][f3l] * w[e][h3];
            }
            __syncthreads();
        }
    }
    __syncthreads();

    float* op = agg + (size_t)d * D1;
    op[c0] = acc0 / (den[h0] + 1e-16f);
    op[c1] = acc1 / (den[h1] + 1e-16f);
    op[c2] = acc2 / (den[h2] + 1e-16f);
    if (c3 < D1) op[c3] = acc3 / (den[h3] + 1e-16f);
}

// ---------------- block-diagonal GEMM + bias + relu -------------------------
// out1[n, h*78+c] = relu( sum_k agg[n, h*78+k] * W1[k, h*78+c] + b1[h*78+c] )
#define BK1 26
__global__ __launch_bounds__(256) void gemm_head(
    const float* __restrict__ agg, const float* __restrict__ W1,
    const float* __restrict__ b1, float* __restrict__ out1)
{
    __shared__ float As[BK1][128];   // transposed: As[k][r]
    __shared__ float Bs[BK1][80];
    int h = blockIdx.y;
    int rowBase = blockIdx.x * 128;
    int tid = threadIdx.x;
    int ty = tid >> 3;            // 0..31 -> 4 rows each
    int tx = tid & 7;             // 0..7  -> 10 cols each (80 padded)
    int r0 = ty * 4;

    float acc[4][10] = {};

    for (int k0 = 0; k0 < FIN; k0 += BK1) {
        for (int idx = tid; idx < 128 * BK1; idx += 256) {
            int r = idx / BK1, c = idx - r * BK1;
            int gr = rowBase + r;
            As[c][r] = (gr < NN) ? agg[(size_t)gr * D1 + h * FIN + k0 + c] : 0.f;
        }
        for (int idx = tid; idx < BK1 * FIN; idx += 256) {
            int r = idx / FIN, c = idx - r * FIN;
            Bs[r][c] = W1[(size_t)(k0 + r) * D1 + h * FIN + c];
        }
        __syncthreads();
        #pragma unroll
        for (int k = 0; k < BK1; k++) {
            float a0 = As[k][r0], a1 = As[k][r0 + 1], a2 = As[k][r0 + 2], a3 = As[k][r0 + 3];
            float b[10];
            #pragma unroll
            for (int j = 0; j < 10; j++) b[j] = Bs[k][tx * 10 + j];
            #pragma unroll
            for (int j = 0; j < 10; j++) {
                acc[0][j] += a0 * b[j];
                acc[1][j] += a1 * b[j];
                acc[2][j] += a2 * b[j];
                acc[3][j] += a3 * b[j];
            }
        }
        __syncthreads();
    }

    #pragma unroll
    for (int i = 0; i < 4; i++) {
        int gr = rowBase + r0 + i;
        if (gr >= NN) continue;
        #pragma unroll
        for (int j = 0; j < 10; j++) {
            int gc = tx * 10 + j;
            if (gc < FIN) {
                float v = acc[i][j] + b1[h * FIN + gc];
                out1[(size_t)gr * D1 + h * FIN + gc] = v > 0.f ? v : 0.f;
            }
        }
    }
}

// ---------------- SGEMM (layer 2): 128x128x16, 8x8 micro --------------------
__global__ __launch_bounds__(256) void sgemm128(
    const float* __restrict__ A, const float* __restrict__ B, float* __restrict__ C,
    int M, int K, int Nn)
{
    __shared__ float As[16][132];
    __shared__ float Bs[16][132];
    int tid = threadIdx.x;
    int tx = tid & 15, ty = tid >> 4;
    int rowBase = blockIdx.y * 128, colBase = blockIdx.x * 128;
    float acc[8][8] = {};
    for (int k0 = 0; k0 < K; k0 += 16) {
        #pragma unroll
        for (int i = 0; i < 8; i++) {
            int idx = tid + i * 256;
            int r = idx >> 4, c = idx & 15;
            int gr = rowBase + r, gc = k0 + c;
            As[c][r] = (gr < M && gc < K) ? A[(size_t)gr * K + gc] : 0.f;
        }
        #pragma unroll
        for (int i = 0; i < 8; i++) {
            int idx = tid + i * 256;
            int r = idx >> 7, c = idx & 127;
            int gr = k0 + r, gc = colBase + c;
            Bs[r][c] = (gr < K && gc < Nn) ? B[(size_t)gr * Nn + gc] : 0.f;
        }
        __syncthreads();
        #pragma unroll
        for (int k = 0; k < 16; k++) {
            float a[8], b[8];
            #pragma unroll
            for (int i = 0; i < 8; i++) a[i] = As[k][ty * 8 + i];
            #pragma unroll
            for (int j = 0; j < 8; j++) b[j] = Bs[k][tx * 8 + j];
            #pragma unroll
            for (int i = 0; i < 8; i++)
                #pragma unroll
                for (int j = 0; j < 8; j++) acc[i][j] += a[i] * b[j];
        }
        __syncthreads();
    }
    #pragma unroll
    for (int i = 0; i < 8; i++) {
        int gr = rowBase + ty * 8 + i;
        if (gr >= M) continue;
        #pragma unroll
        for (int j = 0; j < 8; j++) {
            int gc = colBase + tx * 8 + j;
            if (gc < Nn) C[(size_t)gr * Nn + gc] = acc[i][j];
        }
    }
}

// ---------------- per-node attention projections (layer 2) ------------------
__global__ void alpha_proj(const float* __restrict__ h,
                           const float* __restrict__ a_src, const float* __restrict__ a_dst,
                           float* __restrict__ as, float* __restrict__ ad,
                           int n, int heads, int dim)
{
    int gw = (blockIdx.x * blockDim.x + threadIdx.x) >> 5;
    int lane = threadIdx.x & 31;
    if (gw >= n * heads) return;
    int node = gw / heads, hd = gw - node * heads;
    const float* hp = h + (size_t)node * heads * dim + (size_t)hd * dim;
    float s1 = 0.f, s2 = 0.f;
    for (int f = lane; f < dim; f += 32) {
        float v = hp[f];
        s1 += v * a_src[hd * dim + f];
        s2 += v * a_dst[hd * dim + f];
    }
    #pragma unroll
    for (int o = 16; o; o >>= 1) {
        s1 += __shfl_down_sync(0xffffffffu, s1, o);
        s2 += __shfl_down_sync(0xffffffffu, s2, o);
    }
    if (lane == 0) { as[gw] = s1; ad[gw] = s2; }
}

// ---------------- layer-2 gather (1 head, 128 feats) ----------------
#define CHUNK2 128
__global__ __launch_bounds__(128) void gat_gather2(
    const int* __restrict__ rowptr, const int* __restrict__ csrsrc,
    const float* __restrict__ as, const float* __restrict__ ad,
    const float* __restrict__ h, const float* __restrict__ bias,
    float* __restrict__ out)
{
    int d = blockIdx.x;
    int tid = threadIdx.x;
    int beg = rowptr[d], end = rowptr[d + 1];
    int deg = end - beg;

    __shared__ float ms, dens;
    __shared__ int   s_src[CHUNK2];
    __shared__ float w[CHUNK2];

    float adv = ad[d];
    if (tid == 0) { ms = -INFINITY; dens = 0.f; }
    __syncthreads();

    float acc = 0.f;

    if (deg <= CHUNK2) {
        if (tid < deg) {
            int s = csrsrc[beg + tid];
            s_src[tid] = s;
            float v = as[s] + adv;
            v = v > 0.f ? v : SLOPE * v;
            w[tid] = v;
            atomicMaxF(&ms, v);
        }
        __syncthreads();
        float mv = ms;
        if (tid < deg) {
            float ww = __expf(w[tid] - mv);
            w[tid] = ww;
            atomicAdd(&dens, ww);
        }
        __syncthreads();
        for (int e = 0; e < deg; e++)
            acc += h[(size_t)s_src[e] * OUT2C + tid] * w[e];
    } else {
        for (int t = tid; t < deg; t += 128) {
            float v = as[csrsrc[beg + t]] + adv;
            v = v > 0.f ? v : SLOPE * v;
            atomicMaxF(&ms, v);
        }
        __syncthreads();
        float mv = ms;
        for (int cbeg = 0; cbeg < deg; cbeg += CHUNK2) {
            int clen = min(CHUNK2, deg - cbeg);
            if (tid < clen) {
                int s = csrsrc[beg + cbeg + tid];
                s_src[tid] = s;
                float v = as[s] + adv;
                v = v > 0.f ? v : SLOPE * v;
                float ww = __expf(v - mv);
                w[tid] = ww;
                atomicAdd(&dens, ww);
            }
            __syncthreads();
            for (int e = 0; e < clen; e++)
                acc += h[(size_t)s_src[e] * OUT2C + tid] * w[e];
            __syncthreads();
        }
    }
    __syncthreads();

    float v = acc / (dens + 1e-16f) + bias[tid];
    out[(size_t)d * OUT2C + tid] = v > 0.f ? v : 0.f;
}

// ---------------- fused pool(max) + fc + relu ----------------
__global__ __launch_bounds__(128) void pool_fc(
    const float* __restrict__ o2, const int* __restrict__ gstart,
    const float* __restrict__ W, const float* __restrict__ b,
    float* __restrict__ out)
{
    __shared__ float p[OUT2C];
    int g = blockIdx.x, j = threadIdx.x;
    int beg = gstart[g], end = gstart[g + 1];
    float acc = -INFINITY;
    for (int n = beg; n < end; n++)
        acc = fmaxf(acc, o2[(size_t)n * OUT2C + j]);
    p[j] = (beg < end) ? acc : 0.f;
    __syncthreads();
    float s = b[j];
    #pragma unroll 8
    for (int k = 0; k < OUT2C; k++) s += p[k] * W[k * OUT2C + j];
    out[g * OUT2C + j] = s > 0.f ? s : 0.f;
}

// ---------------- launch ----------------
static inline int cdiv(int a, int b) { return (a + b - 1) / b; }

extern "C" void kernel_launch(void* const* d_in, const int* in_sizes, int n_in,
                              void* d_out, int out_size)
{
    const float* x     = (const float*)d_in[0];
    const int*   ei    = (const int*)  d_in[1];
    const int*   batch = (const int*)  d_in[2];
    const float* W1    = (const float*)d_in[4];
    const float* a_s1  = (const float*)d_in[5];
    const float* a_d1  = (const float*)d_in[6];
    const float* b1    = (const float*)d_in[7];
    const float* W2    = (const float*)d_in[8];
    const float* a_s2  = (const float*)d_in[9];
    const float* a_d2  = (const float*)d_in[10];
    const float* b2    = (const float*)d_in[11];
    const float* fcW   = (const float*)d_in[12];
    const float* fcb   = (const float*)d_in[13];
    float* out = (float*)d_out;

    float *agg, *o1, *h2, *o2, *as1, *ad1, *as2, *ad2, *pvec;
    int *deg, *rowptr, *cursor, *csrsrc, *gstart;
    cudaGetSymbolAddress((void**)&agg, g_agg);
    cudaGetSymbolAddress((void**)&o1,  g_o1);
    cudaGetSymbolAddress((void**)&h2,  g_h2);
    cudaGetSymbolAddress((void**)&o2,  g_o2);
    cudaGetSymbolAddress((void**)&as1, g_as1);
    cudaGetSymbolAddress((void**)&ad1, g_ad1);
    cudaGetSymbolAddress((void**)&as2, g_as2);
    cudaGetSymbolAddress((void**)&ad2, g_ad2);
    cudaGetSymbolAddress((void**)&pvec, g_p);
    cudaGetSymbolAddress((void**)&deg,    g_deg);
    cudaGetSymbolAddress((void**)&rowptr, g_rowptr);
    cudaGetSymbolAddress((void**)&cursor, g_cursor);
    cudaGetSymbolAddress((void**)&csrsrc, g_csrsrc);
    cudaGetSymbolAddress((void**)&gstart, g_gstart);

    // 1-3: CSR build (deg zero on entry; see zero_deg cleanup)
    hist_kernel<<<cdiv(ETOT, 256), 256>>>(ei, deg);                 // 1
    scan50k<<<1, 1024>>>(deg, rowptr, cursor);                      // 2
    csr_scatter<<<cdiv(ETOT, 256), 256>>>(ei, cursor, csrsrc);      // 3

    // ---- layer 1 (restructured: aggregate x, then block-diag GEMM) ----
    precompute_p<<<cdiv(20 * FIN, 256), 256>>>(W1, a_s1, a_d1, pvec);        // 4
    proj1<<<cdiv(NN, 32), 256>>>(x, pvec, as1, ad1);                         // 5
    gather1x<<<NN, 256>>>(rowptr, csrsrc, as1, ad1, x, agg);                 // 6 <- ncu
    {
        dim3 grid(cdiv(NN, 128), H1C);
        gemm_head<<<grid, 256>>>(agg, W1, b1, o1);                           // 7
    }

    // ---- layer 2 ----
    {
        dim3 grid(cdiv(OUT2C, 128), cdiv(NN, 128));
        sgemm128<<<grid, 256>>>(o1, W2, h2, NN, D1, OUT2C);                  // 8
    }
    alpha_proj<<<cdiv(NN * 32, 256), 256>>>(h2, a_s2, a_d2, as2, ad2, NN, 1, OUT2C); // 9
    gat_gather2<<<NN, 128>>>(rowptr, csrsrc, as2, ad2, h2, b2, o2);          // 10

    // ---- pool + fc ----
    gstart_build<<<cdiv(NN, 256), 256>>>(batch, gstart);                     // 11
    pool_fc<<<GC, OUT2C>>>(o2, gstart, fcW, fcb, out);                       // 12

    // cleanup for next replay
    zero_deg<<<cdiv(NN + 1, 256), 256>>>(deg);                               // 13
}

// round 7
// speedup vs baseline: 1.5801x; 1.1767x over previous
#include <cuda_runtime.h>
#include <cuda_bf16.h>
#include <cuda_pipeline.h>
#include <mma.h>
#include <math.h>

using namespace nvcuda;

#define NN    50000
#define EE    800000
#define ETOT  (EE + NN)
#define FIN   78
#define H1C   10
#define D1    (H1C * FIN)   // 780
#define OUT2C 128
#define GC    512
#define SLOPE 0.2f
#define CHUNK 64
#define PROJ_BLOCKS ((NN + 31) / 32)       // 1563
#define EDGE_BLOCKS ((ETOT + 255) / 256)   // 3321

// ---------------- scratch ----------------
__device__ float g_agg[(size_t)NN * D1];
__device__ float g_o1 [(size_t)NN * D1];
__device__ float g_h2 [(size_t)NN * OUT2C];
__device__ float g_o2 [(size_t)NN * OUT2C];
__device__ float g_as1[(size_t)NN * H1C];
__device__ float g_ad1[(size_t)NN * H1C];
__device__ float g_as2[NN];
__device__ float g_ad2[NN];
__device__ float g_p  [20 * FIN];
__device__ int   g_deg[NN + 1];            // zero-init; re-zeroed by cleanup
__device__ int   g_rowptr[NN + 1];
__device__ int   g_cursor[NN];
__device__ int   g_csrsrc[ETOT];
__device__ int   g_gstart[GC + 1];

// ---------------- helpers ----------------
__device__ __forceinline__ void atomicMaxF(float* addr, float val) {
    if (!signbit(val)) atomicMax((int*)addr, __float_as_int(val));
    else               atomicMin((unsigned int*)addr, __float_as_uint(val));
}
__device__ __forceinline__ void edge_nodes(const int* __restrict__ ei, int t, int& s, int& d) {
    if (t < EE) { s = ei[t]; d = ei[EE + t]; }
    else        { s = t - EE; d = t - EE; }
}

// ---------------- 1: histogram ----------------
__global__ void hist_kernel(const int* __restrict__ ei, int* __restrict__ deg) {
    int t = blockIdx.x * blockDim.x + threadIdx.x;
    if (t >= ETOT) return;
    int s, d; edge_nodes(ei, t, s, d);
    atomicAdd(&deg[d], 1);
}

// ---------------- 2: scan (+ attention-vector projection p) ----------------
__global__ void scan50k(const int* __restrict__ deg, int* __restrict__ rowptr,
                        int* __restrict__ cur,
                        const float* __restrict__ W1, const float* __restrict__ a_src,
                        const float* __restrict__ a_dst, float* __restrict__ p)
{
    // p[o*78+k] = sum_f W1[k, h*78+f] * a_{src|dst}[h][f]
    for (int idx = threadIdx.x; idx < 20 * FIN; idx += 1024) {
        int o = idx / FIN, k = idx - o * FIN;
        int h = (o < H1C) ? o : o - H1C;
        const float* av = (o < H1C) ? (a_src + h * FIN) : (a_dst + h * FIN);
        const float* wrow = W1 + (size_t)k * D1 + h * FIN;
        float s = 0.f;
        #pragma unroll 13
        for (int f = 0; f < FIN; f++) s += wrow[f] * av[f];
        p[idx] = s;
    }

    __shared__ int sh[1024];
    __shared__ int carry_s;
    int tid = threadIdx.x;
    if (tid == 0) carry_s = 0;
    __syncthreads();
    for (int base = 0; base < NN; base += 1024) {
        int i = base + tid;
        int v = (i < NN) ? deg[i] : 0;
        sh[tid] = v;
        __syncthreads();
        #pragma unroll
        for (int o = 1; o < 1024; o <<= 1) {
            int t = (tid >= o) ? sh[tid - o] : 0;
            __syncthreads();
            sh[tid] += t;
            __syncthreads();
        }
        int c = carry_s;
        if (i < NN) {
            int excl = c + sh[tid] - v;
            rowptr[i] = excl;
            cur[i] = excl;
        }
        __syncthreads();
        if (tid == 0) carry_s = c + sh[1023];
        __syncthreads();
    }
    if (tid == 0) rowptr[NN] = carry_s;
}

// ---------------- 3: CSR scatter + per-node logits as1/ad1 ------------------
__global__ __launch_bounds__(256) void csr_scatter_proj(
    const int* __restrict__ ei, int* __restrict__ cur, int* __restrict__ csrsrc,
    const float* __restrict__ x, const float* __restrict__ p,
    float* __restrict__ as, float* __restrict__ ad)
{
    int b = blockIdx.x, tid = threadIdx.x;
    int t = b * 256 + tid;
    if (t < ETOT) {
        int s, d; edge_nodes(ei, t, s, d);
        int pos = atomicAdd(&cur[d], 1);
        csrsrc[pos] = s;
    }

    if (b < PROJ_BLOCKS) {
        __shared__ float xs[32][80];
        __shared__ float ps[20][80];
        int nodeBase = b * 32;
        for (int idx = tid; idx < 20 * FIN; idx += 256) {
            int o = idx / FIN, k = idx - o * FIN;
            ps[o][k] = p[idx];
        }
        for (int idx = tid; idx < 32 * FIN; idx += 256) {
            int i = idx / FIN, k = idx - i * FIN;
            int n = nodeBase + i;
            xs[i][k] = (n < NN) ? x[(size_t)n * FIN + k] : 0.f;
        }
        __syncthreads();
        for (int s = tid; s < 32 * 20; s += 256) {
            int i = s / 20, o = s - i * 20;
            int n = nodeBase + i;
            if (n >= NN) continue;
            float acc = 0.f;
            #pragma unroll 13
            for (int k = 0; k < FIN; k++) acc += xs[i][k] * ps[o][k];
            if (o < H1C) as[n * H1C + o] = acc;
            else         ad[n * H1C + (o - H1C)] = acc;
        }
    }
}

// ---------------- 4: layer-1 gather (aggregate x rows) ----------------------
__global__ __launch_bounds__(256) void gather1x(
    const int* __restrict__ rowptr, const int* __restrict__ csrsrc,
    const float* __restrict__ as, const float* __restrict__ ad,
    const float* __restrict__ x, float* __restrict__ agg)
{
    int d = blockIdx.x;
    int tid = threadIdx.x;
    int beg = rowptr[d], end = rowptr[d + 1];
    int deg = end - beg;

    __shared__ float m[H1C];
    __shared__ float den[H1C];
    __shared__ float adv[H1C];
    __shared__ int   s_src[CHUNK];
    __shared__ float w[CHUNK][H1C];
    __shared__ float xs[CHUNK][80];

    if (tid < H1C) {
        adv[tid] = ad[d * H1C + tid];
        m[tid] = -INFINITY;
        den[tid] = 0.f;
    }
    __syncthreads();

    int c0 = tid, c1 = tid + 256, c2 = tid + 512, c3 = tid + 768;
    int h0 = c0 / FIN, f0l = c0 - h0 * FIN;
    int h1 = c1 / FIN, f1l = c1 - h1 * FIN;
    int h2 = c2 / FIN, f2l = c2 - h2 * FIN;
    int h3 = (c3 < D1) ? c3 / FIN : 0, f3l = (c3 < D1) ? c3 - h3 * FIN : 0;
    float acc0 = 0.f, acc1 = 0.f, acc2 = 0.f, acc3 = 0.f;

    if (deg <= CHUNK) {
        for (int t = tid; t < deg; t += 256) s_src[t] = csrsrc[beg + t];
        __syncthreads();
        for (int t = tid; t < deg * FIN; t += 256) {
            int e = t / FIN, k = t - e * FIN;
            xs[e][k] = x[(size_t)s_src[e] * FIN + k];
        }
        for (int t = tid; t < deg * H1C; t += 256) {
            int e = t / H1C, hh = t - e * H1C;
            float v = as[s_src[e] * H1C + hh] + adv[hh];
            v = v > 0.f ? v : SLOPE * v;
            w[e][hh] = v;
            atomicMaxF(&m[hh], v);
        }
        __syncthreads();
        for (int t = tid; t < deg * H1C; t += 256) {
            int e = t / H1C, hh = t - e * H1C;
            float ww = __expf(w[e][hh] - m[hh]);
            w[e][hh] = ww;
            atomicAdd(&den[hh], ww);
        }
        __syncthreads();
        for (int e = 0; e < deg; e++) {
            acc0 += xs[e][f0l] * w[e][h0];
            acc1 += xs[e][f1l] * w[e][h1];
            acc2 += xs[e][f2l] * w[e][h2];
            if (c3 < D1) acc3 += xs[e][f3l] * w[e][h3];
        }
    } else {
        for (int t = tid; t < deg * H1C; t += 256) {
            int e = t / H1C, hh = t - e * H1C;
            int s = csrsrc[beg + e];
            float v = as[s * H1C + hh] + adv[hh];
            v = v > 0.f ? v : SLOPE * v;
            atomicMaxF(&m[hh], v);
        }
        __syncthreads();
        for (int cbeg = 0; cbeg < deg; cbeg += CHUNK) {
            int clen = min(CHUNK, deg - cbeg);
            for (int t = tid; t < clen; t += 256) s_src[t] = csrsrc[beg + cbeg + t];
            __syncthreads();
            for (int t = tid; t < clen * FIN; t += 256) {
                int e = t / FIN, k = t - e * FIN;
                xs[e][k] = x[(size_t)s_src[e] * FIN + k];
            }
            for (int t = tid; t < clen * H1C; t += 256) {
                int e = t / H1C, hh = t - e * H1C;
                float v = as[s_src[e] * H1C + hh] + adv[hh];
                v = v > 0.f ? v : SLOPE * v;
                float ww = __expf(v - m[hh]);
                w[e][hh] = ww;
                atomicAdd(&den[hh], ww);
            }
            __syncthreads();
            for (int e = 0; e < clen; e++) {
                acc0 += xs[e][f0l] * w[e][h0];
                acc1 += xs[e][f1l] * w[e][h1];
                acc2 += xs[e][f2l] * w[e][h2];
                if (c3 < D1) acc3 += xs[e][f3l] * w[e][h3];
            }
            __syncthreads();
        }
    }
    __syncthreads();

    float* op = agg + (size_t)d * D1;
    op[c0] = acc0 / (den[h0] + 1e-16f);
    op[c1] = acc1 / (den[h1] + 1e-16f);
    op[c2] = acc2 / (den[h2] + 1e-16f);
    if (c3 < D1) op[c3] = acc3 / (den[h3] + 1e-16f);
}

// ---------------- 5: block-diagonal GEMM + bias + relu ----------------------
#define BK1 26
__global__ __launch_bounds__(256) void gemm_head(
    const float* __restrict__ agg, const float* __restrict__ W1,
    const float* __restrict__ b1, float* __restrict__ out1)
{
    __shared__ float As[BK1][128];
    __shared__ float Bs[BK1][80];
    int h = blockIdx.y;
    int rowBase = blockIdx.x * 128;
    int tid = threadIdx.x;
    int ty = tid >> 3;
    int tx = tid & 7;
    int r0 = ty * 4;

    float acc[4][10] = {};

    for (int k0 = 0; k0 < FIN; k0 += BK1) {
        for (int idx = tid; idx < 128 * BK1; idx += 256) {
            int r = idx / BK1, c = idx - r * BK1;
            int gr = rowBase + r;
            As[c][r] = (gr < NN) ? agg[(size_t)gr * D1 + h * FIN + k0 + c] : 0.f;
        }
        for (int idx = tid; idx < BK1 * FIN; idx += 256) {
            int r = idx / FIN, c = idx - r * FIN;
            Bs[r][c] = W1[(size_t)(k0 + r) * D1 + h * FIN + c];
        }
        __syncthreads();
        #pragma unroll
        for (int k = 0; k < BK1; k++) {
            float a0 = As[k][r0], a1 = As[k][r0 + 1], a2 = As[k][r0 + 2], a3 = As[k][r0 + 3];
            float b[10];
            #pragma unroll
            for (int j = 0; j < 10; j++) b[j] = Bs[k][tx * 10 + j];
            #pragma unroll
            for (int j = 0; j < 10; j++) {
                acc[0][j] += a0 * b[j];
                acc[1][j] += a1 * b[j];
                acc[2][j] += a2 * b[j];
                acc[3][j] += a3 * b[j];
            }
        }
        __syncthreads();
    }

    #pragma unroll
    for (int i = 0; i < 4; i++) {
        int gr = rowBase + r0 + i;
        if (gr >= NN) continue;
        #pragma unroll
        for (int j = 0; j < 10; j++) {
            int gc = tx * 10 + j;
            if (gc < FIN) {
                float v = acc[i][j] + b1[h * FIN + gc];
                out1[(size_t)gr * D1 + h * FIN + gc] = v > 0.f ? v : 0.f;
            }
        }
    }
}

// ---------------- 6: layer-2 GEMM, TF32 tensor cores, cp.async pipeline -----
// C[M,128] = A[M,780] @ B[780,128]. Block 128 rows; 8 warps, warp 32x64.
#define K2    780
#define NCH   49          // ceil(780/16)
#define LDAS  20          // 16 + 4 pad (floats); 80B rows, 16B aligned
#define LDBS  136         // 128 + 8 pad; 544B rows, 16B aligned

__global__ __launch_bounds__(256) void gemm2_tf32(
    const float* __restrict__ A, const float* __restrict__ B, float* __restrict__ C, int M)
{
    __shared__ float As[2][128][LDAS];
    __shared__ float Bs[2][16][LDBS];

    int tid = threadIdx.x;
    int warp = tid >> 5;
    int warp_m = warp & 3;
    int warp_n = warp >> 2;
    int rowBase = blockIdx.x * 128;

    wmma::fragment<wmma::accumulator, 16, 16, 8, float> acc[2][4];
    #pragma unroll
    for (int i = 0; i < 2; i++)
        #pragma unroll
        for (int j = 0; j < 4; j++) wmma::fill_fragment(acc[i][j], 0.f);

    // stage loader: chunk ch -> buffer buf
    auto load_stage = [&](int ch, int buf) {
        int k0 = ch * 16;
        // A: 128 rows x 16 floats = 512 x 16B chunks
        #pragma unroll
        for (int l = 0; l < 2; l++) {
            int idx = tid + l * 256;
            int r = idx >> 2, c4 = idx & 3;
            int gr = rowBase + r;
            int gk = k0 + c4 * 4;
            bool valid = (gr < M) && (gk < K2);
            const float* src = A + (size_t)gr * K2 + gk;
            __pipeline_memcpy_async(&As[buf][r][c4 * 4], src, 16, valid ? 0 : 16);
        }
        // B: 16 rows x 128 floats = 512 x 16B chunks
        #pragma unroll
        for (int l = 0; l < 2; l++) {
            int idx = tid + l * 256;
            int r = idx >> 5, c = idx & 31;
            int gk = k0 + r;
            bool valid = (gk < K2);
            const float* src = B + (size_t)gk * OUT2C + c * 4;
            __pipeline_memcpy_async(&Bs[buf][r][c * 4], src, 16, valid ? 0 : 16);
        }
        __pipeline_commit();
    };

    load_stage(0, 0);

    for (int ch = 0; ch < NCH; ch++) {
        int buf = ch & 1;
        if (ch + 1 < NCH) load_stage(ch + 1, (ch + 1) & 1);
        __pipeline_wait_prior((ch + 1 < NCH) ? 1 : 0);
        __syncthreads();

        #pragma unroll
        for (int kk = 0; kk < 16; kk += 8) {
            wmma::fragment<wmma::matrix_a, 16, 16, 8, wmma::precision::tf32, wmma::row_major> af[2];
            wmma::fragment<wmma::matrix_b, 16, 16, 8, wmma::precision::tf32, wmma::row_major> bf[4];
            #pragma unroll
            for (int i = 0; i < 2; i++) {
                wmma::load_matrix_sync(af[i], &As[buf][warp_m * 32 + i * 16][kk], LDAS);
                #pragma unroll
                for (int t = 0; t < af[i].num_elements; t++)
                    af[i].x[t] = wmma::__float_to_tf32(af[i].x[t]);
            }
            #pragma unroll
            for (int j = 0; j < 4; j++) {
                wmma::load_matrix_sync(bf[j], &Bs[buf][kk][warp_n * 64 + j * 16], LDBS);
                #pragma unroll
                for (int t = 0; t < bf[j].num_elements; t++)
                    bf[j].x[t] = wmma::__float_to_tf32(bf[j].x[t]);
            }
            #pragma unroll
            for (int i = 0; i < 2; i++)
                #pragma unroll
                for (int j = 0; j < 4; j++)
                    wmma::mma_sync(acc[i][j], af[i], bf[j], acc[i][j]);
        }
        __syncthreads();
    }

    // epilogue: M % 16 == 0, so each fragment is wholly valid or wholly OOB
    #pragma unroll
    for (int i = 0; i < 2; i++) {
        int gr = rowBase + warp_m * 32 + i * 16;
        if (gr >= M) continue;
        #pragma unroll
        for (int j = 0; j < 4; j++) {
            int gc = warp_n * 64 + j * 16;
            wmma::store_matrix_sync(&C[(size_t)gr * OUT2C + gc], acc[i][j], OUT2C, wmma::mem_row_major);
        }
    }
}

// ---------------- 7: layer-2 attention projections --------------------------
__global__ void alpha_proj(const float* __restrict__ h,
                           const float* __restrict__ a_src, const float* __restrict__ a_dst,
                           float* __restrict__ as, float* __restrict__ ad,
                           int n, int heads, int dim)
{
    int gw = (blockIdx.x * blockDim.x + threadIdx.x) >> 5;
    int lane = threadIdx.x & 31;
    if (gw >= n * heads) return;
    int node = gw / heads, hd = gw - node * heads;
    const float* hp = h + (size_t)node * heads * dim + (size_t)hd * dim;
    float s1 = 0.f, s2 = 0.f;
    for (int f = lane; f < dim; f += 32) {
        float v = hp[f];
        s1 += v * a_src[hd * dim + f];
        s2 += v * a_dst[hd * dim + f];
    }
    #pragma unroll
    for (int o = 16; o; o >>= 1) {
        s1 += __shfl_down_sync(0xffffffffu, s1, o);
        s2 += __shfl_down_sync(0xffffffffu, s2, o);
    }
    if (lane == 0) { as[gw] = s1; ad[gw] = s2; }
}

// ---------------- 8: layer-2 gather ----------------
#define CHUNK2 128
__global__ __launch_bounds__(128) void gat_gather2(
    const int* __restrict__ rowptr, const int* __restrict__ csrsrc,
    const float* __restrict__ as, const float* __restrict__ ad,
    const float* __restrict__ h, const float* __restrict__ bias,
    float* __restrict__ out)
{
    int d = blockIdx.x;
    int tid = threadIdx.x;
    int beg = rowptr[d], end = rowptr[d + 1];
    int deg = end - beg;

    __shared__ float ms, dens;
    __shared__ int   s_src[CHUNK2];
    __shared__ float w[CHUNK2];

    float adv = ad[d];
    if (tid == 0) { ms = -INFINITY; dens = 0.f; }
    __syncthreads();

    float acc = 0.f;

    if (deg <= CHUNK2) {
        if (tid < deg) {
            int s = csrsrc[beg + tid];
            s_src[tid] = s;
            float v = as[s] + adv;
            v = v > 0.f ? v : SLOPE * v;
            w[tid] = v;
            atomicMaxF(&ms, v);
        }
        __syncthreads();
        float mv = ms;
        if (tid < deg) {
            float ww = __expf(w[tid] - mv);
            w[tid] = ww;
            atomicAdd(&dens, ww);
        }
        __syncthreads();
        for (int e = 0; e < deg; e++)
            acc += h[(size_t)s_src[e] * OUT2C + tid] * w[e];
    } else {
        for (int t = tid; t < deg; t += 128) {
            float v = as[csrsrc[beg + t]] + adv;
            v = v > 0.f ? v : SLOPE * v;
            atomicMaxF(&ms, v);
        }
        __syncthreads();
        float mv = ms;
        for (int cbeg = 0; cbeg < deg; cbeg += CHUNK2) {
            int clen = min(CHUNK2, deg - cbeg);
            if (tid < clen) {
                int s = csrsrc[beg + cbeg + tid];
                s_src[tid] = s;
                float v = as[s] + adv;
                v = v > 0.f ? v : SLOPE * v;
                float ww = __expf(v - mv);
                w[tid] = ww;
                atomicAdd(&dens, ww);
            }
            __syncthreads();
            for (int e = 0; e < clen; e++)
                acc += h[(size_t)s_src[e] * OUT2C + tid] * w[e];
            __syncthreads();
        }
    }
    __syncthreads();

    float v = acc / (dens + 1e-16f) + bias[tid];
    out[(size_t)d * OUT2C + tid] = v > 0.f ? v : 0.f;
}

// ---------------- 9: gstart ----------------
__global__ void gstart_build(const int* __restrict__ batch, int* __restrict__ gstart) {
    int i = blockIdx.x * blockDim.x + threadIdx.x;
    if (i >= NN) return;
    int b  = batch[i];
    int bp = (i == 0) ? -1 : batch[i - 1];
    for (int g = bp + 1; g <= b; ++g) gstart[g] = i;
    if (i == NN - 1) {
        for (int g = b + 1; g <= GC; ++g) gstart[g] = NN;
    }
}

// ---------------- 10: fused pool(max) + fc + relu ----------------
__global__ __launch_bounds__(128) void pool_fc(
    const float* __restrict__ o2, const int* __restrict__ gstart,
    const float* __restrict__ W, const float* __restrict__ b,
    float* __restrict__ out)
{
    __shared__ float p[OUT2C];
    int g = blockIdx.x, j = threadIdx.x;
    int beg = gstart[g], end = gstart[g + 1];
    float acc = -INFINITY;
    for (int n = beg; n < end; n++)
        acc = fmaxf(acc, o2[(size_t)n * OUT2C + j]);
    p[j] = (beg < end) ? acc : 0.f;
    __syncthreads();
    float s = b[j];
    #pragma unroll 8
    for (int k = 0; k < OUT2C; k++) s += p[k] * W[k * OUT2C + j];
    out[g * OUT2C + j] = s > 0.f ? s : 0.f;
}

// ---------------- 11: cleanup ----------------
__global__ void zero_deg(int* __restrict__ deg) {
    int i = blockIdx.x * blockDim.x + threadIdx.x;
    if (i < NN + 1) deg[i] = 0;
}

// ---------------- launch ----------------
static inline int cdiv(int a, int b) { return (a + b - 1) / b; }

extern "C" void kernel_launch(void* const* d_in, const int* in_sizes, int n_in,
                              void* d_out, int out_size)
{
    const float* x     = (const float*)d_in[0];
    const int*   ei    = (const int*)  d_in[1];
    const int*   batch = (const int*)  d_in[2];
    const float* W1    = (const float*)d_in[4];
    const float* a_s1  = (const float*)d_in[5];
    const float* a_d1  = (const float*)d_in[6];
    const float* b1    = (const float*)d_in[7];
    const float* W2    = (const float*)d_in[8];
    const float* a_s2  = (const float*)d_in[9];
    const float* a_d2  = (const float*)d_in[10];
    const float* b2    = (const float*)d_in[11];
    const float* fcW   = (const float*)d_in[12];
    const float* fcb   = (const float*)d_in[13];
    float* out = (float*)d_out;

    float *agg, *o1, *h2, *o2, *as1, *ad1, *as2, *ad2, *pvec;
    int *deg, *rowptr, *cursor, *csrsrc, *gstart;
    cudaGetSymbolAddress((void**)&agg, g_agg);
    cudaGetSymbolAddress((void**)&o1,  g_o1);
    cudaGetSymbolAddress((void**)&h2,  g_h2);
    cudaGetSymbolAddress((void**)&o2,  g_o2);
    cudaGetSymbolAddress((void**)&as1, g_as1);
    cudaGetSymbolAddress((void**)&ad1, g_ad1);
    cudaGetSymbolAddress((void**)&as2, g_as2);
    cudaGetSymbolAddress((void**)&ad2, g_ad2);
    cudaGetSymbolAddress((void**)&pvec, g_p);
    cudaGetSymbolAddress((void**)&deg,    g_deg);
    cudaGetSymbolAddress((void**)&rowptr, g_rowptr);
    cudaGetSymbolAddress((void**)&cursor, g_cursor);
    cudaGetSymbolAddress((void**)&csrsrc, g_csrsrc);
    cudaGetSymbolAddress((void**)&gstart, g_gstart);

    hist_kernel<<<EDGE_BLOCKS, 256>>>(ei, deg);                              // 1
    scan50k<<<1, 1024>>>(deg, rowptr, cursor, W1, a_s1, a_d1, pvec);         // 2
    csr_scatter_proj<<<EDGE_BLOCKS, 256>>>(ei, cursor, csrsrc, x, pvec, as1, ad1); // 3
    gather1x<<<NN, 256>>>(rowptr, csrsrc, as1, ad1, x, agg);                 // 4 <- ncu
    {
        dim3 grid(cdiv(NN, 128), H1C);
        gemm_head<<<grid, 256>>>(agg, W1, b1, o1);                           // 5
    }
    gemm2_tf32<<<cdiv(NN, 128), 256>>>(o1, W2, h2, NN);                      // 6
    alpha_proj<<<cdiv(NN * 32, 256), 256>>>(h2, a_s2, a_d2, as2, ad2, NN, 1, OUT2C); // 7
    gat_gather2<<<NN, 128>>>(rowptr, csrsrc, as2, ad2, h2, b2, o2);          // 8
    gstart_build<<<cdiv(NN, 256), 256>>>(batch, gstart);                     // 9
    pool_fc<<<GC, OUT2C>>>(o2, gstart, fcW, fcb, out);                       // 10
    zero_deg<<<cdiv(NN + 1, 256), 256>>>(deg);                               // 11
}

// round 9
// speedup vs baseline: 1.7019x; 1.0771x over previous
#include <cuda_runtime.h>
#include <cuda_bf16.h>
#include <cuda_pipeline.h>
#include <mma.h>
#include <math.h>

using namespace nvcuda;

#define NN    50000
#define EE    800000
#define ETOT  (EE + NN)
#define FIN   78
#define H1C   10
#define D1    (H1C * FIN)   // 780
#define OUT2C 128
#define GC    512
#define SLOPE 0.2f
#define CHUNK 64
#define PROJ_BLOCKS ((NN + 31) / 32)       // 1563
#define EDGE_BLOCKS ((ETOT + 255) / 256)   // 3321

// ---------------- scratch ----------------
__device__ float g_agg[(size_t)NN * D1];
__device__ float g_o1 [(size_t)NN * D1];
__device__ float g_h2 [(size_t)NN * OUT2C];
__device__ float g_o2 [(size_t)NN * OUT2C];
__device__ float g_as1[(size_t)NN * H1C];
__device__ float g_ad1[(size_t)NN * H1C];
__device__ float g_as2[NN];
__device__ float g_ad2[NN];
__device__ float g_p  [20 * FIN];
__device__ int   g_deg[NN + 1];            // zero-init; re-zeroed by cleanup
__device__ int   g_rowptr[NN + 1];
__device__ int   g_cursor[NN];
__device__ int   g_csrsrc[ETOT];
__device__ int   g_gstart[GC + 1];

// ---------------- helpers ----------------
__device__ __forceinline__ void atomicMaxF(float* addr, float val) {
    if (!signbit(val)) atomicMax((int*)addr, __float_as_int(val));
    else               atomicMin((unsigned int*)addr, __float_as_uint(val));
}
__device__ __forceinline__ void edge_nodes(const int* __restrict__ ei, int t, int& s, int& d) {
    if (t < EE) { s = ei[t]; d = ei[EE + t]; }
    else        { s = t - EE; d = t - EE; }
}

// ---------------- 1: histogram ----------------
__global__ void hist_kernel(const int* __restrict__ ei, int* __restrict__ deg) {
    int t = blockIdx.x * blockDim.x + threadIdx.x;
    if (t >= ETOT) return;
    int s, d; edge_nodes(ei, t, s, d);
    atomicAdd(&deg[d], 1);
}

// ---------------- 2: scan (+ attention-vector projection p) ----------------
__global__ void scan50k(const int* __restrict__ deg, int* __restrict__ rowptr,
                        int* __restrict__ cur,
                        const float* __restrict__ W1, const float* __restrict__ a_src,
                        const float* __restrict__ a_dst, float* __restrict__ p)
{
    for (int idx = threadIdx.x; idx < 20 * FIN; idx += 1024) {
        int o = idx / FIN, k = idx - o * FIN;
        int h = (o < H1C) ? o : o - H1C;
        const float* av = (o < H1C) ? (a_src + h * FIN) : (a_dst + h * FIN);
        const float* wrow = W1 + (size_t)k * D1 + h * FIN;
        float s = 0.f;
        #pragma unroll 13
        for (int f = 0; f < FIN; f++) s += wrow[f] * av[f];
        p[idx] = s;
    }

    __shared__ int sh[1024];
    __shared__ int carry_s;
    int tid = threadIdx.x;
    if (tid == 0) carry_s = 0;
    __syncthreads();
    for (int base = 0; base < NN; base += 1024) {
        int i = base + tid;
        int v = (i < NN) ? deg[i] : 0;
        sh[tid] = v;
        __syncthreads();
        #pragma unroll
        for (int o = 1; o < 1024; o <<= 1) {
            int t = (tid >= o) ? sh[tid - o] : 0;
            __syncthreads();
            sh[tid] += t;
            __syncthreads();
        }
        int c = carry_s;
        if (i < NN) {
            int excl = c + sh[tid] - v;
            rowptr[i] = excl;
            cur[i] = excl;
        }
        __syncthreads();
        if (tid == 0) carry_s = c + sh[1023];
        __syncthreads();
    }
    if (tid == 0) rowptr[NN] = carry_s;
}

// ---------------- 3: CSR scatter + per-node logits as1/ad1 ------------------
__global__ __launch_bounds__(256) void csr_scatter_proj(
    const int* __restrict__ ei, int* __restrict__ cur, int* __restrict__ csrsrc,
    const float* __restrict__ x, const float* __restrict__ p,
    float* __restrict__ as, float* __restrict__ ad)
{
    int b = blockIdx.x, tid = threadIdx.x;
    int t = b * 256 + tid;
    if (t < ETOT) {
        int s, d; edge_nodes(ei, t, s, d);
        int pos = atomicAdd(&cur[d], 1);
        csrsrc[pos] = s;
    }

    if (b < PROJ_BLOCKS) {
        __shared__ float xs[32][80];
        __shared__ float ps[20][80];
        int nodeBase = b * 32;
        for (int idx = tid; idx < 20 * FIN; idx += 256) {
            int o = idx / FIN, k = idx - o * FIN;
            ps[o][k] = p[idx];
        }
        for (int idx = tid; idx < 32 * FIN; idx += 256) {
            int i = idx / FIN, k = idx - i * FIN;
            int n = nodeBase + i;
            xs[i][k] = (n < NN) ? x[(size_t)n * FIN + k] : 0.f;
        }
        __syncthreads();
        for (int s = tid; s < 32 * 20; s += 256) {
            int i = s / 20, o = s - i * 20;
            int n = nodeBase + i;
            if (n >= NN) continue;
            float acc = 0.f;
            #pragma unroll 13
            for (int k = 0; k < FIN; k++) acc += xs[i][k] * ps[o][k];
            if (o < H1C) as[n * H1C + o] = acc;
            else         ad[n * H1C + (o - H1C)] = acc;
        }
    }
}

// ---------------- 4: layer-1 gather (aggregate x rows, float4 LDS) ----------
// 200 active threads: hh = tid/20 (head), f4 = (tid%20)*4 (feature block)
__global__ __launch_bounds__(256) void gather1x(
    const int* __restrict__ rowptr, const int* __restrict__ csrsrc,
    const float* __restrict__ as, const float* __restrict__ ad,
    const float* __restrict__ x, float* __restrict__ agg)
{
    int d = blockIdx.x;
    int tid = threadIdx.x;
    int beg = rowptr[d], end = rowptr[d + 1];
    int deg = end - beg;

    __shared__ float m[H1C];
    __shared__ float den[H1C];
    __shared__ float adv[H1C];
    __shared__ int   s_src[CHUNK];
    __shared__ float w[CHUNK][H1C];
    __shared__ __align__(16) float xs[CHUNK][80];

    if (tid < H1C) {
        adv[tid] = ad[d * H1C + tid];
        m[tid] = -INFINITY;
        den[tid] = 0.f;
    }
    __syncthreads();

    const bool active = tid < 200;
    int hh = tid / 20;
    int f4 = (tid % 20) * 4;
    float a0 = 0.f, a1 = 0.f, a2 = 0.f, a3 = 0.f;

    if (deg <= CHUNK) {
        for (int t = tid; t < deg; t += 256) s_src[t] = csrsrc[beg + t];
        __syncthreads();
        // stage x rows (padded cols 78,79 zeroed)
        for (int t = tid; t < deg * FIN; t += 256) {
            int e = t / FIN, k = t - e * FIN;
            xs[e][k] = x[(size_t)s_src[e] * FIN + k];
        }
        for (int t = tid; t < deg * 2; t += 256) xs[t >> 1][FIN + (t & 1)] = 0.f;
        // logits
        for (int t = tid; t < deg * H1C; t += 256) {
            int e = t / H1C, h = t - e * H1C;
            float v = as[s_src[e] * H1C + h] + adv[h];
            v = v > 0.f ? v : SLOPE * v;
            w[e][h] = v;
            atomicMaxF(&m[h], v);
        }
        __syncthreads();
        for (int t = tid; t < deg * H1C; t += 256) {
            int e = t / H1C, h = t - e * H1C;
            float ww = __expf(w[e][h] - m[h]);
            w[e][h] = ww;
            atomicAdd(&den[h], ww);
        }
        __syncthreads();
        if (active) {
            for (int e = 0; e < deg; e++) {
                float4 xv = *(const float4*)&xs[e][f4];
                float ww = w[e][hh];
                a0 += xv.x * ww; a1 += xv.y * ww; a2 += xv.z * ww; a3 += xv.w * ww;
            }
        }
    } else {
        // max pass over all edges
        for (int t = tid; t < deg * H1C; t += 256) {
            int e = t / H1C, h = t - e * H1C;
            int s = csrsrc[beg + e];
            float v = as[s * H1C + h] + adv[h];
            v = v > 0.f ? v : SLOPE * v;
            atomicMaxF(&m[h], v);
        }
        __syncthreads();
        for (int cbeg = 0; cbeg < deg; cbeg += CHUNK) {
            int clen = min(CHUNK, deg - cbeg);
            for (int t = tid; t < clen; t += 256) s_src[t] = csrsrc[beg + cbeg + t];
            __syncthreads();
            for (int t = tid; t < clen * FIN; t += 256) {
                int e = t / FIN, k = t - e * FIN;
                xs[e][k] = x[(size_t)s_src[e] * FIN + k];
            }
            for (int t = tid; t < clen * 2; t += 256) xs[t >> 1][FIN + (t & 1)] = 0.f;
            for (int t = tid; t < clen * H1C; t += 256) {
                int e = t / H1C, h = t - e * H1C;
                float v = as[s_src[e] * H1C + h] + adv[h];
                v = v > 0.f ? v : SLOPE * v;
                float ww = __expf(v - m[h]);
                w[e][h] = ww;
                atomicAdd(&den[h], ww);
            }
            __syncthreads();
            if (active) {
                for (int e = 0; e < clen; e++) {
                    float4 xv = *(const float4*)&xs[e][f4];
                    float ww = w[e][hh];
                    a0 += xv.x * ww; a1 += xv.y * ww; a2 += xv.z * ww; a3 += xv.w * ww;
                }
            }
            __syncthreads();
        }
    }
    __syncthreads();

    if (active) {
        float inv = 1.f / (den[hh] + 1e-16f);
        float* op = agg + (size_t)d * D1 + hh * FIN + f4;
        op[0] = a0 * inv;
        if (f4 + 1 < FIN) op[1] = a1 * inv;
        if (f4 + 2 < FIN) op[2] = a2 * inv;
        if (f4 + 3 < FIN) op[3] = a3 * inv;
    }
}

// ---------------- 5: block-diagonal GEMM + bias + relu ----------------------
#define BK1 26
__global__ __launch_bounds__(256) void gemm_head(
    const float* __restrict__ agg, const float* __restrict__ W1,
    const float* __restrict__ b1, float* __restrict__ out1)
{
    __shared__ float As[BK1][128];
    __shared__ float Bs[BK1][80];
    int h = blockIdx.y;
    int rowBase = blockIdx.x * 128;
    int tid = threadIdx.x;
    int ty = tid >> 3;
    int tx = tid & 7;
    int r0 = ty * 4;

    float acc[4][10] = {};

    for (int k0 = 0; k0 < FIN; k0 += BK1) {
        for (int idx = tid; idx < 128 * BK1; idx += 256) {
            int r = idx / BK1, c = idx - r * BK1;
            int gr = rowBase + r;
            As[c][r] = (gr < NN) ? agg[(size_t)gr * D1 + h * FIN + k0 + c] : 0.f;
        }
        for (int idx = tid; idx < BK1 * FIN; idx += 256) {
            int r = idx / FIN, c = idx - r * FIN;
            Bs[r][c] = W1[(size_t)(k0 + r) * D1 + h * FIN + c];
        }
        __syncthreads();
        #pragma unroll
        for (int k = 0; k < BK1; k++) {
            float a0 = As[k][r0], a1 = As[k][r0 + 1], a2 = As[k][r0 + 2], a3 = As[k][r0 + 3];
            float b[10];
            #pragma unroll
            for (int j = 0; j < 10; j++) b[j] = Bs[k][tx * 10 + j];
            #pragma unroll
            for (int j = 0; j < 10; j++) {
                acc[0][j] += a0 * b[j];
                acc[1][j] += a1 * b[j];
                acc[2][j] += a2 * b[j];
                acc[3][j] += a3 * b[j];
            }
        }
        __syncthreads();
    }

    #pragma unroll
    for (int i = 0; i < 4; i++) {
        int gr = rowBase + r0 + i;
        if (gr >= NN) continue;
        #pragma unroll
        for (int j = 0; j < 10; j++) {
            int gc = tx * 10 + j;
            if (gc < FIN) {
                float v = acc[i][j] + b1[h * FIN + gc];
                out1[(size_t)gr * D1 + h * FIN + gc] = v > 0.f ? v : 0.f;
            }
        }
    }
}

// ---------------- 6: layer-2 GEMM, TF32 tensor cores, cp.async pipeline -----
#define K2    780
#define NCH   49
#define LDAS  20
#define LDBS  136

__global__ __launch_bounds__(256) void gemm2_tf32(
    const float* __restrict__ A, const float* __restrict__ B, float* __restrict__ C, int M)
{
    __shared__ float As[2][128][LDAS];
    __shared__ float Bs[2][16][LDBS];

    int tid = threadIdx.x;
    int warp = tid >> 5;
    int warp_m = warp & 3;
    int warp_n = warp >> 2;
    int rowBase = blockIdx.x * 128;

    wmma::fragment<wmma::accumulator, 16, 16, 8, float> acc[2][4];
    #pragma unroll
    for (int i = 0; i < 2; i++)
        #pragma unroll
        for (int j = 0; j < 4; j++) wmma::fill_fragment(acc[i][j], 0.f);

    auto load_stage = [&](int ch, int buf) {
        int k0 = ch * 16;
        #pragma unroll
        for (int l = 0; l < 2; l++) {
            int idx = tid + l * 256;
            int r = idx >> 2, c4 = idx & 3;
            int gr = rowBase + r;
            int gk = k0 + c4 * 4;
            bool valid = (gr < M) && (gk < K2);
            const float* src = A + (size_t)gr * K2 + gk;
            __pipeline_memcpy_async(&As[buf][r][c4 * 4], src, 16, valid ? 0 : 16);
        }
        #pragma unroll
        for (int l = 0; l < 2; l++) {
            int idx = tid + l * 256;
            int r = idx >> 5, c = idx & 31;
            int gk = k0 + r;
            bool valid = (gk < K2);
            const float* src = B + (size_t)gk * OUT2C + c * 4;
            __pipeline_memcpy_async(&Bs[buf][r][c * 4], src, 16, valid ? 0 : 16);
        }
        __pipeline_commit();
    };

    load_stage(0, 0);

    for (int ch = 0; ch < NCH; ch++) {
        int buf = ch & 1;
        if (ch + 1 < NCH) load_stage(ch + 1, (ch + 1) & 1);
        __pipeline_wait_prior((ch + 1 < NCH) ? 1 : 0);
        __syncthreads();

        #pragma unroll
        for (int kk = 0; kk < 16; kk += 8) {
            wmma::fragment<wmma::matrix_a, 16, 16, 8, wmma::precision::tf32, wmma::row_major> af[2];
            wmma::fragment<wmma::matrix_b, 16, 16, 8, wmma::precision::tf32, wmma::row_major> bf[4];
            #pragma unroll
            for (int i = 0; i < 2; i++) {
                wmma::load_matrix_sync(af[i], &As[buf][warp_m * 32 + i * 16][kk], LDAS);
                #pragma unroll
                for (int t = 0; t < af[i].num_elements; t++)
                    af[i].x[t] = wmma::__float_to_tf32(af[i].x[t]);
            }
            #pragma unroll
            for (int j = 0; j < 4; j++) {
                wmma::load_matrix_sync(bf[j], &Bs[buf][kk][warp_n * 64 + j * 16], LDBS);
                #pragma unroll
                for (int t = 0; t < bf[j].num_elements; t++)
                    bf[j].x[t] = wmma::__float_to_tf32(bf[j].x[t]);
            }
            #pragma unroll
            for (int i = 0; i < 2; i++)
                #pragma unroll
                for (int j = 0; j < 4; j++)
                    wmma::mma_sync(acc[i][j], af[i], bf[j], acc[i][j]);
        }
        __syncthreads();
    }

    #pragma unroll
    for (int i = 0; i < 2; i++) {
        int gr = rowBase + warp_m * 32 + i * 16;
        if (gr >= M) continue;
        #pragma unroll
        for (int j = 0; j < 4; j++) {
            int gc = warp_n * 64 + j * 16;
            wmma::store_matrix_sync(&C[(size_t)gr * OUT2C + gc], acc[i][j], OUT2C, wmma::mem_row_major);
        }
    }
}

// ---------------- 7: layer-2 attention projections --------------------------
__global__ void alpha_proj(const float* __restrict__ h,
                           const float* __restrict__ a_src, const float* __restrict__ a_dst,
                           float* __restrict__ as, float* __restrict__ ad,
                           int n, int heads, int dim)
{
    int gw = (blockIdx.x * blockDim.x + threadIdx.x) >> 5;
    int lane = threadIdx.x & 31;
    if (gw >= n * heads) return;
    int node = gw / heads, hd = gw - node * heads;
    const float* hp = h + (size_t)node * heads * dim + (size_t)hd * dim;
    float s1 = 0.f, s2 = 0.f;
    for (int f = lane; f < dim; f += 32) {
        float v = hp[f];
        s1 += v * a_src[hd * dim + f];
        s2 += v * a_dst[hd * dim + f];
    }
    #pragma unroll
    for (int o = 16; o; o >>= 1) {
        s1 += __shfl_down_sync(0xffffffffu, s1, o);
        s2 += __shfl_down_sync(0xffffffffu, s2, o);
    }
    if (lane == 0) { as[gw] = s1; ad[gw] = s2; }
}

// ---------------- 8: layer-2 gather ----------------
#define CHUNK2 128
__global__ __launch_bounds__(128) void gat_gather2(
    const int* __restrict__ rowptr, const int* __restrict__ csrsrc,
    const float* __restrict__ as, const float* __restrict__ ad,
    const float* __restrict__ h, const float* __restrict__ bias,
    float* __restrict__ out)
{
    int d = blockIdx.x;
    int tid = threadIdx.x;
    int beg = rowptr[d], end = rowptr[d + 1];
    int deg = end - beg;

    __shared__ float ms, dens;
    __shared__ int   s_src[CHUNK2];
    __shared__ float w[CHUNK2];

    float adv = ad[d];
    if (tid == 0) { ms = -INFINITY; dens = 0.f; }
    __syncthreads();

    float acc = 0.f;

    if (deg <= CHUNK2) {
        if (tid < deg) {
            int s = csrsrc[beg + tid];
            s_src[tid] = s;
            float v = as[s] + adv;
            v = v > 0.f ? v : SLOPE * v;
            w[tid] = v;
            atomicMaxF(&ms, v);
        }
        __syncthreads();
        float mv = ms;
        if (tid < deg) {
            float ww = __expf(w[tid] - mv);
            w[tid] = ww;
            atomicAdd(&dens, ww);
        }
        __syncthreads();
        for (int e = 0; e < deg; e++)
            acc += h[(size_t)s_src[e] * OUT2C + tid] * w[e];
    } else {
        for (int t = tid; t < deg; t += 128) {
            float v = as[csrsrc[beg + t]] + adv;
            v = v > 0.f ? v : SLOPE * v;
            atomicMaxF(&ms, v);
        }
        __syncthreads();
        float mv = ms;
        for (int cbeg = 0; cbeg < deg; cbeg += CHUNK2) {
            int clen = min(CHUNK2, deg - cbeg);
            if (tid < clen) {
                int s = csrsrc[beg + cbeg + tid];
                s_src[tid] = s;
                float v = as[s] + adv;
                v = v > 0.f ? v : SLOPE * v;
                float ww = __expf(v - mv);
                w[tid] = ww;
                atomicAdd(&dens, ww);
            }
            __syncthreads();
            for (int e = 0; e < clen; e++)
                acc += h[(size_t)s_src[e] * OUT2C + tid] * w[e];
            __syncthreads();
        }
    }
    __syncthreads();

    float v = acc / (dens + 1e-16f) + bias[tid];
    out[(size_t)d * OUT2C + tid] = v > 0.f ? v : 0.f;
}

// ---------------- 9: gstart ----------------
__global__ void gstart_build(const int* __restrict__ batch, int* __restrict__ gstart) {
    int i = blockIdx.x * blockDim.x + threadIdx.x;
    if (i >= NN) return;
    int b  = batch[i];
    int bp = (i == 0) ? -1 : batch[i - 1];
    for (int g = bp + 1; g <= b; ++g) gstart[g] = i;
    if (i == NN - 1) {
        for (int g = b + 1; g <= GC; ++g) gstart[g] = NN;
    }
}

// ---------------- 10: fused pool(max) + fc + relu ----------------
__global__ __launch_bounds__(128) void pool_fc(
    const float* __restrict__ o2, const int* __restrict__ gstart,
    const float* __restrict__ W, const float* __restrict__ b,
    float* __restrict__ out)
{
    __shared__ float p[OUT2C];
    int g = blockIdx.x, j = threadIdx.x;
    int beg = gstart[g], end = gstart[g + 1];
    float acc = -INFINITY;
    for (int n = beg; n < end; n++)
        acc = fmaxf(acc, o2[(size_t)n * OUT2C + j]);
    p[j] = (beg < end) ? acc : 0.f;
    __syncthreads();
    float s = b[j];
    #pragma unroll 8
    for (int k = 0; k < OUT2C; k++) s += p[k] * W[k * OUT2C + j];
    out[g * OUT2C + j] = s > 0.f ? s : 0.f;
}

// ---------------- 11: cleanup ----------------
__global__ void zero_deg(int* __restrict__ deg) {
    int i = blockIdx.x * blockDim.x + threadIdx.x;
    if (i < NN + 1) deg[i] = 0;
}

// ---------------- launch ----------------
static inline int cdiv(int a, int b) { return (a + b - 1) / b; }

extern "C" void kernel_launch(void* const* d_in, const int* in_sizes, int n_in,
                              void* d_out, int out_size)
{
    const float* x     = (const float*)d_in[0];
    const int*   ei    = (const int*)  d_in[1];
    const int*   batch = (const int*)  d_in[2];
    const float* W1    = (const float*)d_in[4];
    const float* a_s1  = (const float*)d_in[5];
    const float* a_d1  = (const float*)d_in[6];
    const float* b1    = (const float*)d_in[7];
    const float* W2    = (const float*)d_in[8];
    const float* a_s2  = (const float*)d_in[9];
    const float* a_d2  = (const float*)d_in[10];
    const float* b2    = (const float*)d_in[11];
    const float* fcW   = (const float*)d_in[12];
    const float* fcb   = (const float*)d_in[13];
    float* out = (float*)d_out;

    float *agg, *o1, *h2, *o2, *as1, *ad1, *as2, *ad2, *pvec;
    int *deg, *rowptr, *cursor, *csrsrc, *gstart;
    cudaGetSymbolAddress((void**)&agg, g_agg);
    cudaGetSymbolAddress((void**)&o1,  g_o1);
    cudaGetSymbolAddress((void**)&h2,  g_h2);
    cudaGetSymbolAddress((void**)&o2,  g_o2);
    cudaGetSymbolAddress((void**)&as1, g_as1);
    cudaGetSymbolAddress((void**)&ad1, g_ad1);
    cudaGetSymbolAddress((void**)&as2, g_as2);
    cudaGetSymbolAddress((void**)&ad2, g_ad2);
    cudaGetSymbolAddress((void**)&pvec, g_p);
    cudaGetSymbolAddress((void**)&deg,    g_deg);
    cudaGetSymbolAddress((void**)&rowptr, g_rowptr);
    cudaGetSymbolAddress((void**)&cursor, g_cursor);
    cudaGetSymbolAddress((void**)&csrsrc, g_csrsrc);
    cudaGetSymbolAddress((void**)&gstart, g_gstart);

    hist_kernel<<<EDGE_BLOCKS, 256>>>(ei, deg);                              // 1
    scan50k<<<1, 1024>>>(deg, rowptr, cursor, W1, a_s1, a_d1, pvec);         // 2
    csr_scatter_proj<<<EDGE_BLOCKS, 256>>>(ei, cursor, csrsrc, x, pvec, as1, ad1); // 3
    gather1x<<<NN, 256>>>(rowptr, csrsrc, as1, ad1, x, agg);                 // 4 <- ncu
    {
        dim3 grid(cdiv(NN, 128), H1C);
        gemm_head<<<grid, 256>>>(agg, W1, b1, o1);                           // 5
    }
    gemm2_tf32<<<cdiv(NN, 128), 256>>>(o1, W2, h2, NN);                      // 6
    alpha_proj<<<cdiv(NN * 32, 256), 256>>>(h2, a_s2, a_d2, as2, ad2, NN, 1, OUT2C); // 7
    gat_gather2<<<NN, 128>>>(rowptr, csrsrc, as2, ad2, h2, b2, o2);          // 8
    gstart_build<<<cdiv(NN, 256), 256>>>(batch, gstart);                     // 9
    pool_fc<<<GC, OUT2C>>>(o2, gstart, fcW, fcb, out);                       // 10
    zero_deg<<<cdiv(NN + 1, 256), 256>>>(deg);                               // 11
}